// round 5
// baseline (speedup 1.0000x reference)
#include <cuda_runtime.h>
#include <cuda_bf16.h>
#include <cstdint>

typedef __nv_bfloat16 bf16;

// ---------------------------------------------------------------------------
// Static scratch: split bf16 activation planes (channels-last), fp32 f1/s0,
// pre-split weights in im2col k-order (k = j*CIN + i).
// z / Wfc1 use permuted k-order: k' = pos*256 + chan for the conv part
// (so conv3's epilogue writes contiguous rows), identity for branch part.
// ---------------------------------------------------------------------------
__device__ __align__(1024) bf16 g_h0h[(size_t)2048 * 255 * 64];
__device__ __align__(1024) bf16 g_h0l[(size_t)2048 * 255 * 64];
__device__ __align__(1024) bf16 g_h1h[(size_t)2048 * 255 * 128];
__device__ __align__(1024) bf16 g_h1l[(size_t)2048 * 255 * 128];
__device__ __align__(1024) bf16 g_h2h[(size_t)2048 * 128 * 256];
__device__ __align__(1024) bf16 g_h2l[(size_t)2048 * 128 * 256];
__device__ __align__(1024) bf16 g_zh [(size_t)2048 * 16640];
__device__ __align__(1024) bf16 g_zl [(size_t)2048 * 16640];
__device__ __align__(1024) float g_f1[(size_t)2048 * 1024];
__device__ __align__(1024) float g_s0[2048 * 64];
__device__ __align__(1024) bf16 g_wah[64 * 64],   g_wal[64 * 64];
__device__ __align__(1024) bf16 g_w1h[128 * 192], g_w1l[128 * 192];
__device__ __align__(1024) bf16 g_w2h[256 * 384], g_w2l[256 * 384];
__device__ __align__(1024) bf16 g_w3h[256 * 768], g_w3l[256 * 768];
__device__ __align__(1024) bf16 g_wfh[(size_t)1024 * 16640];
__device__ __align__(1024) bf16 g_wfl[(size_t)1024 * 16640];

// ---------------------------------------------------------------------------
// Helpers (baseline PTX only: mma.sync / ldmatrix / cp.async — no tcgen05)
// ---------------------------------------------------------------------------
__device__ __forceinline__ uint32_t cvta_smem(const void* p) {
    return (uint32_t)__cvta_generic_to_shared(p);
}
__device__ __forceinline__ void cpa16(uint32_t dst, const void* src, int sz) {
    asm volatile("cp.async.cg.shared.global [%0], [%1], 16, %2;"
                 :: "r"(dst), "l"(src), "r"(sz) : "memory");
}
__device__ __forceinline__ void cp_commit() {
    asm volatile("cp.async.commit_group;" ::: "memory");
}
#define LDM4(r, addr)                                                         \
    asm volatile("ldmatrix.sync.aligned.m8n8.x4.shared.b16 "                  \
                 "{%0,%1,%2,%3}, [%4];"                                       \
                 : "=r"((r)[0]), "=r"((r)[1]), "=r"((r)[2]), "=r"((r)[3])     \
                 : "r"(addr))

__device__ __forceinline__ void mma16816(float* d, const uint32_t* a,
                                         uint32_t b0, uint32_t b1) {
    asm volatile(
        "mma.sync.aligned.m16n8k16.row.col.f32.bf16.bf16.f32 "
        "{%0,%1,%2,%3}, {%4,%5,%6,%7}, {%8,%9}, {%0,%1,%2,%3};"
        : "+f"(d[0]), "+f"(d[1]), "+f"(d[2]), "+f"(d[3])
        : "r"(a[0]), "r"(a[1]), "r"(a[2]), "r"(a[3]), "r"(b0), "r"(b1));
}
__device__ __forceinline__ void split2(float v, bf16& h, bf16& l) {
    h = __float2bfloat16(v);
    l = __float2bfloat16(v - __bfloat162float(h));
}
__device__ __forceinline__ uint32_t pack2(bf16 a, bf16 b) {
    return (uint32_t)__bfloat16_as_ushort(a) |
           ((uint32_t)__bfloat16_as_ushort(b) << 16);
}

// ---------------------------------------------------------------------------
// Unified split-bf16 mma.sync GEMM with fused im2col gather.
// D[m,n] = relu(sum_k A(m,k)*B(n,k) + bias); m=(b,p); k=(j,i); r=STRIDE*p+j+ROFF
// CTA tile 128 x NT, BK=64, 8 warps (4M x 2N), warp tile 32 x NT/2.
// 3-stage cp.async pipeline, one __syncthreads per k-iter.
// OUTMODE: 0 = out[m*NS + n]; 2 = z layout out[b*16640 + p*256 + n].
// ---------------------------------------------------------------------------
template<int KTOT, int NT, int CIN, int LIN, int LOUT, int STRIDE, int ROFF,
         int OUTMODE, int NS, bool ROWBIAS, bool AF32, bool OUTF32>
__global__ void __launch_bounds__(256, 1)
gemm_kernel(const float* __restrict__ Af32,
            const bf16* __restrict__ Ahi, const bf16* __restrict__ Alo,
            const bf16* __restrict__ Whi, const bf16* __restrict__ Wlo,
            const float* __restrict__ bias,
            float* __restrict__ Of32, bf16* __restrict__ Ohi,
            bf16* __restrict__ Olo)
{
    constexpr int BK = 64;
    constexpr int NITER = KTOT / BK;
    constexpr int ASZ = 128 * 128;            // bytes: 128 rows x 128B (one plane)
    constexpr int BSZ = NT * 128;
    constexpr int BUFB = 2 * ASZ + 2 * BSZ;
    constexpr int NH = NT / 2;                // n per warp
    constexpr int NI = NH / 8;                // n8 tiles per warp
    constexpr int NL = NH / 16;               // ldmatrix.x4 calls per plane

    extern __shared__ __align__(1024) char smem_c[];
    const uint32_t smem0 = cvta_smem(smem_c);

    const int tid = threadIdx.x;
    const int lane = tid & 31;
    const int wid = tid >> 5;
    const int warpM = wid >> 1;
    const int warpN = wid & 1;
    const int n0 = blockIdx.x * NT;
    const int m0 = blockIdx.y * 128;

    float acc[2][NI][4];
    #pragma unroll
    for (int mt = 0; mt < 2; ++mt)
        #pragma unroll
        for (int nt = 0; nt < NI; ++nt)
            #pragma unroll
            for (int e = 0; e < 4; ++e) acc[mt][nt][e] = 0.f;

    // ---- loaders -----------------------------------------------------------
    auto load_tiles = [&](int it, int buf) {
        const int k0 = it * BK;
        const uint32_t sb = smem0 + buf * BUFB;
        #pragma unroll
        for (int rep = 0; rep < 4; ++rep) {           // A: 128 rows x 8 x 16B
            int v = tid + rep * 256;
            int row = v >> 3, q = v & 7;
            int m = m0 + row;
            int b = m / LOUT, p = m - b * LOUT;
            int k = k0 + q * 8;
            int j = k / CIN, i = k - j * CIN;
            int r = STRIDE * p + j + ROFF;
            bool ok = (r >= 0) && (r < LIN);
            size_t off = (size_t)b * ((size_t)LIN * CIN) + (size_t)r * CIN + i;
            uint32_t so = row * 128 + ((q * 16) ^ ((row & 7) << 4));
            int sz = ok ? 16 : 0;
            cpa16(sb + so, Ahi + off, sz);
            cpa16(sb + ASZ + so, Alo + off, sz);
        }
        #pragma unroll
        for (int rep = 0; rep < NT / 32; ++rep) {     // B: NT rows x 8 x 16B
            int v = tid + rep * 256;
            int n = v >> 3, q = v & 7;
            size_t off = (size_t)(n0 + n) * KTOT + k0 + q * 8;
            uint32_t so = n * 128 + ((q * 16) ^ ((n & 7) << 4));
            cpa16(sb + 2 * ASZ + so, Whi + off, 16);
            cpa16(sb + 2 * ASZ + BSZ + so, Wlo + off, 16);
        }
    };

    if constexpr (AF32) {
        // stage-A: single K-tile, fp32 -> split bf16 in registers, sync stores
        #pragma unroll
        for (int rep = 0; rep < 8; ++rep) {           // 128 rows x 16 x 8B
            int v = tid + rep * 256;
            int row = v >> 4, q = v & 15;
            int m = m0 + row;
            int b = m / LOUT, p = m - b * LOUT;
            int i = q * 4;
            int r = p + ROFF;
            bool ok = (r >= 0) && (r < LIN);
            float4 val = ok ? *reinterpret_cast<const float4*>(
                                  Af32 + (size_t)b * ((size_t)LIN * CIN) +
                                  (size_t)r * CIN + i)
                            : make_float4(0.f, 0.f, 0.f, 0.f);
            bf16 h0, h1, h2, h3, l0, l1, l2, l3;
            split2(val.x, h0, l0); split2(val.y, h1, l1);
            split2(val.z, h2, l2); split2(val.w, h3, l3);
            uint32_t so = row * 128 + ((q * 8) ^ ((row & 7) << 4));
            *reinterpret_cast<uint2*>(smem_c + so) =
                make_uint2(pack2(h0, h1), pack2(h2, h3));
            *reinterpret_cast<uint2*>(smem_c + ASZ + so) =
                make_uint2(pack2(l0, l1), pack2(l2, l3));
        }
        #pragma unroll
        for (int rep = 0; rep < NT / 32; ++rep) {     // B sync copy
            int v = tid + rep * 256;
            int n = v >> 3, q = v & 7;
            size_t off = (size_t)(n0 + n) * KTOT + q * 8;
            uint32_t so = n * 128 + ((q * 16) ^ ((n & 7) << 4));
            *reinterpret_cast<uint4*>(smem_c + 2 * ASZ + so) =
                *reinterpret_cast<const uint4*>(Whi + off);
            *reinterpret_cast<uint4*>(smem_c + 2 * ASZ + BSZ + so) =
                *reinterpret_cast<const uint4*>(Wlo + off);
        }
        __syncthreads();
    } else {
        load_tiles(0, 0);
        cp_commit();
        if (NITER > 1) load_tiles(1, 1);
        cp_commit();
    }

    // ---- per-lane ldmatrix addressing constants ----------------------------
    const uint32_t aSwz = (uint32_t)(lane & 7) << 4;
    const uint32_t kbBase = (uint32_t)(lane >> 4) << 4;
    uint32_t rowA[2], rowB[NL];
    #pragma unroll
    for (int mt = 0; mt < 2; ++mt)
        rowA[mt] = (uint32_t)(warpM * 32 + mt * 16 + (lane & 15)) * 128;
    #pragma unroll
    for (int c = 0; c < NL; ++c)
        rowB[c] = (uint32_t)(warpN * NH + c * 16 + (lane & 15)) * 128;

    // ---- mainloop: 3-stage pipeline, one sync per iter ---------------------
    for (int it = 0; it < NITER; ++it) {
        int buf;
        if constexpr (!AF32) {
            buf = it % 3;
            if (it + 2 < NITER) {
                asm volatile("cp.async.wait_group 1;" ::: "memory");
            } else {
                asm volatile("cp.async.wait_group 0;" ::: "memory");
            }
            __syncthreads();
            if (it + 2 < NITER) {
                load_tiles(it + 2, (it + 2) % 3);
                cp_commit();
            }
        } else {
            buf = 0;
        }

        const uint32_t sAh = smem0 + buf * BUFB;
        const uint32_t sAl = sAh + ASZ;
        const uint32_t sBh = sAl + ASZ;
        const uint32_t sBl = sBh + BSZ;

        #pragma unroll
        for (int ks = 0; ks < 4; ++ks) {
            const uint32_t kb = ((uint32_t)(ks * 32) + kbBase) ^ aSwz;
            uint32_t ah[2][4], al[2][4];
            #pragma unroll
            for (int mt = 0; mt < 2; ++mt) {
                LDM4(ah[mt], sAh + rowA[mt] + kb);
                LDM4(al[mt], sAl + rowA[mt] + kb);
            }
            #pragma unroll
            for (int c = 0; c < NL; ++c) {
                uint32_t bh[4], bl[4];
                LDM4(bh, sBh + rowB[c] + kb);
                LDM4(bl, sBl + rowB[c] + kb);
                #pragma unroll
                for (int mt = 0; mt < 2; ++mt) {
                    mma16816(acc[mt][2 * c + 0], ah[mt], bh[0], bh[2]);
                    mma16816(acc[mt][2 * c + 1], ah[mt], bh[1], bh[3]);
                    mma16816(acc[mt][2 * c + 0], ah[mt], bl[0], bl[2]);
                    mma16816(acc[mt][2 * c + 1], ah[mt], bl[1], bl[3]);
                    mma16816(acc[mt][2 * c + 0], al[mt], bh[0], bh[2]);
                    mma16816(acc[mt][2 * c + 1], al[mt], bh[1], bh[3]);
                }
            }
        }
    }

    // ---- epilogue (register accumulators) ----------------------------------
    const int tr = lane >> 2;
    const int tc = (lane & 3) * 2;
    #pragma unroll
    for (int mt = 0; mt < 2; ++mt) {
        #pragma unroll
        for (int half = 0; half < 2; ++half) {     // d0,d1 then d2,d3 (row+8)
            const int m = m0 + warpM * 32 + mt * 16 + tr + half * 8;
            const int bb = m / LOUT;
            const int pp = m - bb * LOUT;
            #pragma unroll
            for (int nt = 0; nt < NI; ++nt) {
                const int n = n0 + warpN * NH + nt * 8 + tc;
                const float d0 = acc[mt][nt][half * 2 + 0];
                const float d1 = acc[mt][nt][half * 2 + 1];
                float b0, b1;
                if constexpr (ROWBIAS) {
                    b0 = bias[(size_t)bb * 64 + n];
                    b1 = bias[(size_t)bb * 64 + n + 1];
                } else {
                    b0 = bias[n];
                    b1 = bias[n + 1];
                }
                const float v0 = fmaxf(d0 + b0, 0.f);
                const float v1 = fmaxf(d1 + b1, 0.f);
                size_t o;
                if constexpr (OUTMODE == 0) {
                    o = (size_t)m * NS + n;
                } else {
                    // z layout: z[b][p*256 + n] (contiguous channels-last)
                    o = (size_t)bb * 16640 + (size_t)pp * 256 + n;
                }
                if constexpr (OUTF32) {
                    *reinterpret_cast<float2*>(Of32 + o) = make_float2(v0, v1);
                } else {
                    bf16 h0, h1, l0, l1;
                    split2(v0, h0, l0);
                    split2(v1, h1, l1);
                    *reinterpret_cast<uint32_t*>(Ohi + o) = pack2(h0, h1);
                    *reinterpret_cast<uint32_t*>(Olo + o) = pack2(l0, l1);
                }
            }
        }
    }
}

// ---------------------------------------------------------------------------
// Fused weight prep: fp32 -> split bf16, im2col k-order; fc1 gets permuted
// k-order matching conv3's z layout (k' = pos*256 + chan for conv part).
// ---------------------------------------------------------------------------
#define PREP_SA   4096
#define PREP_C1   (128 * 192)
#define PREP_C2   (256 * 384)
#define PREP_C3   (256 * 768)
#define PREP_FC   (1024 * 16640)
#define PREP_TOT  (PREP_SA + PREP_C1 + PREP_C2 + PREP_C3 + PREP_FC)

__global__ void prep_all_kernel(
    const float* __restrict__ Wp, const float* __restrict__ W1,
    const float* __restrict__ W2, const float* __restrict__ W3,
    const float* __restrict__ Wfc1,
    bf16* wah, bf16* wal, bf16* w1h, bf16* w1l, bf16* w2h, bf16* w2l,
    bf16* w3h, bf16* w3l, bf16* wfh, bf16* wfl)
{
    int idx = blockIdx.x * 256 + threadIdx.x;
    if (idx >= PREP_TOT) return;
    bf16 h, l;
    if (idx < PREP_SA) {
        int p = idx >> 6, i = idx & 63;
        split2(Wp[p * 128 + i * 2 + 1], h, l);
        wah[idx] = h; wal[idx] = l;
        return;
    }
    idx -= PREP_SA;
    if (idx < PREP_C1) {
        int o = idx / 192, rem = idx - o * 192;
        int i = rem / 3, j = rem - i * 3;
        split2(W1[idx], h, l);
        int out = o * 192 + j * 64 + i;
        w1h[out] = h; w1l[out] = l;
        return;
    }
    idx -= PREP_C1;
    if (idx < PREP_C2) {
        int o = idx / 384, rem = idx - o * 384;
        int i = rem / 3, j = rem - i * 3;
        split2(W2[idx], h, l);
        int out = o * 384 + j * 128 + i;
        w2h[out] = h; w2l[out] = l;
        return;
    }
    idx -= PREP_C2;
    if (idx < PREP_C3) {
        int o = idx / 768, rem = idx - o * 768;
        int i = rem / 3, j = rem - i * 3;
        split2(W3[idx], h, l);
        int out = o * 768 + j * 256 + i;
        w3h[out] = h; w3l[out] = l;
        return;
    }
    idx -= PREP_C3;
    {
        int n = idx / 16640, k2 = idx - n * 16640;
        int old_k;
        if (k2 < 16384) {
            int p = k2 >> 8, c = k2 & 255;   // k' = p*256 + c
            old_k = c * 64 + p;              // reference flatten: c*64 + p
        } else {
            old_k = k2;
        }
        split2(Wfc1[(size_t)n * 16640 + old_k], h, l);
        wfh[idx] = h; wfl[idx] = l;
    }
}

// s0[b][p] = bp[p] + sum_i Wp[p][i][0] * x[b][0][i]
__global__ void __launch_bounds__(64) s0_kernel(
    const float* __restrict__ x, const float* __restrict__ Wp,
    const float* __restrict__ bp, float* __restrict__ s0)
{
    __shared__ float xs[64];
    int b = blockIdx.x, t = threadIdx.x;
    xs[t] = x[(size_t)b * 16384 + t];
    __syncthreads();
    float acc = bp[t];
    #pragma unroll 16
    for (int i = 0; i < 64; ++i) acc += Wp[t * 128 + i * 2] * xs[i];
    s0[b * 64 + t] = acc;
}

// Branch MLP -> split z[:,16384:]
__global__ void __launch_bounds__(256) branch_kernel(
    const float* __restrict__ x,
    const float* __restrict__ Wb1, const float* __restrict__ bb1,
    const float* __restrict__ Wb2, const float* __restrict__ bb2,
    const float* __restrict__ Wb3, const float* __restrict__ bb3,
    bf16* __restrict__ zh, bf16* __restrict__ zl)
{
    __shared__ float x0s[64], f1s[64], f2s[128];
    const int tid = threadIdx.x, b = blockIdx.x;
    if (tid < 64) x0s[tid] = x[(size_t)b * 16384 + tid];
    __syncthreads();
    if (tid < 64) {
        float acc = bb1[tid];
        #pragma unroll 8
        for (int i = 0; i < 64; i++) acc += Wb1[tid * 64 + i] * x0s[i];
        f1s[tid] = fmaxf(acc, 0.f);
    }
    __syncthreads();
    if (tid < 128) {
        float acc = bb2[tid];
        #pragma unroll 8
        for (int i = 0; i < 64; i++) acc += Wb2[tid * 64 + i] * f1s[i];
        f2s[tid] = fmaxf(acc, 0.f);
    }
    __syncthreads();
    {
        float acc = bb3[tid];
        #pragma unroll 8
        for (int i = 0; i < 128; i++) acc += Wb3[tid * 128 + i] * f2s[i];
        float v = fmaxf(acc, 0.f);
        bf16 h, l;
        split2(v, h, l);
        size_t o = (size_t)b * 16640 + 16384 + tid;
        zh[o] = h; zl[o] = l;
    }
}

// fc2
__global__ void __launch_bounds__(128) fc2_kernel(
    const float* __restrict__ f1, const float* __restrict__ W,
    const float* __restrict__ bias, float* __restrict__ out)
{
    __shared__ float red0[4], red1[4];
    const int b = blockIdx.x, tid = threadIdx.x;
    const float* hb = f1 + (size_t)b * 1024;
    float s0 = 0.f, s1 = 0.f;
    for (int k = tid; k < 1024; k += 128) {
        float v = hb[k];
        s0 += v * W[k];
        s1 += v * W[1024 + k];
    }
    #pragma unroll
    for (int off = 16; off > 0; off >>= 1) {
        s0 += __shfl_down_sync(0xffffffffu, s0, off);
        s1 += __shfl_down_sync(0xffffffffu, s1, off);
    }
    if ((tid & 31) == 0) { red0[tid >> 5] = s0; red1[tid >> 5] = s1; }
    __syncthreads();
    if (tid == 0) {
        out[b * 2 + 0] = red0[0] + red0[1] + red0[2] + red0[3] + bias[0];
        out[b * 2 + 1] = red1[0] + red1[1] + red1[2] + red1[3] + bias[1];
    }
}

// ---------------------------------------------------------------------------
// Launch
// ---------------------------------------------------------------------------
extern "C" void kernel_launch(void* const* d_in, const int* in_sizes, int n_in,
                              void* d_out, int out_size)
{
    const float* x    = (const float*)d_in[0];
    const float* Wp   = (const float*)d_in[1];
    const float* bp   = (const float*)d_in[2];
    const float* W1   = (const float*)d_in[3];
    const float* b1   = (const float*)d_in[4];
    const float* W2   = (const float*)d_in[5];
    const float* b2   = (const float*)d_in[6];
    const float* W3   = (const float*)d_in[7];
    const float* b3   = (const float*)d_in[8];
    const float* Wb1  = (const float*)d_in[9];
    const float* bb1  = (const float*)d_in[10];
    const float* Wb2  = (const float*)d_in[11];
    const float* bb2  = (const float*)d_in[12];
    const float* Wb3  = (const float*)d_in[13];
    const float* bb3  = (const float*)d_in[14];
    const float* Wfc1 = (const float*)d_in[15];
    const float* bfc1 = (const float*)d_in[16];
    const float* Wfc2 = (const float*)d_in[17];
    const float* bfc2 = (const float*)d_in[18];
    float* out = (float*)d_out;

    static void *h0h, *h0l, *h1h, *h1l, *h2h, *h2l, *zh, *zl, *f1, *s0;
    static void *wah, *wal, *w1h, *w1l, *w2h, *w2l, *w3h, *w3l, *wfh, *wfl;
    static bool init = false;
    if (!init) {
        cudaGetSymbolAddress(&h0h, g_h0h); cudaGetSymbolAddress(&h0l, g_h0l);
        cudaGetSymbolAddress(&h1h, g_h1h); cudaGetSymbolAddress(&h1l, g_h1l);
        cudaGetSymbolAddress(&h2h, g_h2h); cudaGetSymbolAddress(&h2l, g_h2l);
        cudaGetSymbolAddress(&zh,  g_zh);  cudaGetSymbolAddress(&zl,  g_zl);
        cudaGetSymbolAddress(&f1,  g_f1);  cudaGetSymbolAddress(&s0,  g_s0);
        cudaGetSymbolAddress(&wah, g_wah); cudaGetSymbolAddress(&wal, g_wal);
        cudaGetSymbolAddress(&w1h, g_w1h); cudaGetSymbolAddress(&w1l, g_w1l);
        cudaGetSymbolAddress(&w2h, g_w2h); cudaGetSymbolAddress(&w2l, g_w2l);
        cudaGetSymbolAddress(&w3h, g_w3h); cudaGetSymbolAddress(&w3l, g_w3l);
        cudaGetSymbolAddress(&wfh, g_wfh); cudaGetSymbolAddress(&wfl, g_wfl);

        auto setsm = [](const void* f, int bytes) {
            cudaFuncSetAttribute(f, cudaFuncAttributeMaxDynamicSharedMemorySize, bytes);
        };
        setsm((const void*)gemm_kernel<64, 64, 64, 256, 255, 1, 1, 0, 64, true, true, false>, 49152);
        setsm((const void*)gemm_kernel<192, 128, 64, 255, 255, 1, -1, 0, 128, false, false, false>, 196608);
        setsm((const void*)gemm_kernel<384, 128, 128, 255, 128, 2, -1, 0, 256, false, false, false>, 196608);
        setsm((const void*)gemm_kernel<768, 128, 256, 128, 64, 2, -1, 2, 0, false, false, false>, 196608);
        setsm((const void*)gemm_kernel<16640, 128, 16640, 1, 1, 1, 0, 0, 1024, false, false, true>, 196608);
        init = true;
    }

    // fused weight prep (single launch)
    prep_all_kernel<<<(PREP_TOT + 255) / 256, 256>>>(
        Wp, W1, W2, W3, Wfc1,
        (bf16*)wah, (bf16*)wal, (bf16*)w1h, (bf16*)w1l, (bf16*)w2h, (bf16*)w2l,
        (bf16*)w3h, (bf16*)w3l, (bf16*)wfh, (bf16*)wfl);

    // small fp32 side paths
    s0_kernel<<<2048, 64>>>(x, Wp, bp, (float*)s0);
    branch_kernel<<<2048, 256>>>(x, Wb1, bb1, Wb2, bb2, Wb3, bb3,
                                 (bf16*)zh, (bf16*)zl);

    // stage-A: A = x cols 1..255 (fp32->split in-kernel), rowbias = s0
    gemm_kernel<64, 64, 64, 256, 255, 1, 1, 0, 64, true, true, false>
        <<<dim3(1, 4080), 256, 49152>>>(
            x, nullptr, nullptr, (const bf16*)wah, (const bf16*)wal,
            (const float*)s0, nullptr, (bf16*)h0h, (bf16*)h0l);

    // conv1
    gemm_kernel<192, 128, 64, 255, 255, 1, -1, 0, 128, false, false, false>
        <<<dim3(1, 4080), 256, 196608>>>(
            nullptr, (const bf16*)h0h, (const bf16*)h0l,
            (const bf16*)w1h, (const bf16*)w1l, b1,
            nullptr, (bf16*)h1h, (bf16*)h1l);

    // conv2
    gemm_kernel<384, 128, 128, 255, 128, 2, -1, 0, 256, false, false, false>
        <<<dim3(2, 2048), 256, 196608>>>(
            nullptr, (const bf16*)h1h, (const bf16*)h1l,
            (const bf16*)w2h, (const bf16*)w2l, b2,
            nullptr, (bf16*)h2h, (bf16*)h2l);

    // conv3 -> z (contiguous channels-last layout, permuted fc1 k-order)
    gemm_kernel<768, 128, 256, 128, 64, 2, -1, 2, 0, false, false, false>
        <<<dim3(2, 1024), 256, 196608>>>(
            nullptr, (const bf16*)h2h, (const bf16*)h2l,
            (const bf16*)w3h, (const bf16*)w3l, b3,
            nullptr, (bf16*)zh, (bf16*)zl);

    // fc1 -> f1 (fp32)
    gemm_kernel<16640, 128, 16640, 1, 1, 1, 0, 0, 1024, false, false, true>
        <<<dim3(8, 16), 256, 196608>>>(
            nullptr, (const bf16*)zh, (const bf16*)zl,
            (const bf16*)wfh, (const bf16*)wfl, bfc1,
            (float*)f1, nullptr, nullptr);

    fc2_kernel<<<2048, 128>>>((const float*)f1, Wfc2, bfc2, out);
}

// round 6
// speedup vs baseline: 1.0197x; 1.0197x over previous
#include <cuda_runtime.h>
#include <cuda_bf16.h>
#include <cstdint>

typedef __nv_bfloat16 bf16;

// ---------------------------------------------------------------------------
// Static scratch: split bf16 activation planes (channels-last), fp32 f1/s0,
// pre-split weights in im2col k-order (k = j*CIN + i).
// z / Wfc1 use permuted k-order: k' = pos*256 + chan for the conv part.
// ---------------------------------------------------------------------------
__device__ __align__(1024) bf16 g_h0h[(size_t)2048 * 255 * 64];
__device__ __align__(1024) bf16 g_h0l[(size_t)2048 * 255 * 64];
__device__ __align__(1024) bf16 g_h1h[(size_t)2048 * 255 * 128];
__device__ __align__(1024) bf16 g_h1l[(size_t)2048 * 255 * 128];
__device__ __align__(1024) bf16 g_h2h[(size_t)2048 * 128 * 256];
__device__ __align__(1024) bf16 g_h2l[(size_t)2048 * 128 * 256];
__device__ __align__(1024) bf16 g_zh [(size_t)2048 * 16640];
__device__ __align__(1024) bf16 g_zl [(size_t)2048 * 16640];
__device__ __align__(1024) float g_f1[(size_t)2048 * 1024];
__device__ __align__(1024) float g_s0[2048 * 64];
__device__ __align__(1024) bf16 g_wah[64 * 64],   g_wal[64 * 64];
__device__ __align__(1024) bf16 g_w1h[128 * 192], g_w1l[128 * 192];
__device__ __align__(1024) bf16 g_w2h[256 * 384], g_w2l[256 * 384];
__device__ __align__(1024) bf16 g_w3h[256 * 768], g_w3l[256 * 768];
__device__ __align__(1024) bf16 g_wfh[(size_t)1024 * 16640];
__device__ __align__(1024) bf16 g_wfl[(size_t)1024 * 16640];

// ---------------------------------------------------------------------------
// Helpers (baseline PTX only: mma.sync / ldmatrix / cp.async — no tcgen05)
// ---------------------------------------------------------------------------
__device__ __forceinline__ uint32_t cvta_smem(const void* p) {
    return (uint32_t)__cvta_generic_to_shared(p);
}
__device__ __forceinline__ void cpa16(uint32_t dst, const void* src, int sz) {
    asm volatile("cp.async.cg.shared.global [%0], [%1], 16, %2;"
                 :: "r"(dst), "l"(src), "r"(sz) : "memory");
}
__device__ __forceinline__ void cp_commit() {
    asm volatile("cp.async.commit_group;" ::: "memory");
}
#define LDM4(r, addr)                                                         \
    asm volatile("ldmatrix.sync.aligned.m8n8.x4.shared.b16 "                  \
                 "{%0,%1,%2,%3}, [%4];"                                       \
                 : "=r"((r)[0]), "=r"((r)[1]), "=r"((r)[2]), "=r"((r)[3])     \
                 : "r"(addr))

__device__ __forceinline__ void mma16816(float* d, const uint32_t* a,
                                         uint32_t b0, uint32_t b1) {
    asm volatile(
        "mma.sync.aligned.m16n8k16.row.col.f32.bf16.bf16.f32 "
        "{%0,%1,%2,%3}, {%4,%5,%6,%7}, {%8,%9}, {%0,%1,%2,%3};"
        : "+f"(d[0]), "+f"(d[1]), "+f"(d[2]), "+f"(d[3])
        : "r"(a[0]), "r"(a[1]), "r"(a[2]), "r"(a[3]), "r"(b0), "r"(b1));
}
__device__ __forceinline__ void split2(float v, bf16& h, bf16& l) {
    h = __float2bfloat16(v);
    l = __float2bfloat16(v - __bfloat162float(h));
}
__device__ __forceinline__ uint32_t pack2(bf16 a, bf16 b) {
    return (uint32_t)__bfloat16_as_ushort(a) |
           ((uint32_t)__bfloat16_as_ushort(b) << 16);
}

// ---------------------------------------------------------------------------
// Unified split-bf16 mma.sync GEMM with fused im2col gather.
// D[m,n] = relu(sum_k A(m,k)*B(n,k) + bias); m=(b,p); k=(j,i); r=STRIDE*p+j+ROFF
// 512 threads, CTA tile 256 x NT, BK=64, 16 warps (8M x 2N), warp 32 x NT/2.
// 2-stage cp.async pipeline. XOR-swizzled SMEM, ldmatrix fragments.
// OUTMODE: 0 = out[m*NS + n]; 2 = z layout out[b*16640 + p*256 + n].
// ---------------------------------------------------------------------------
template<int KTOT, int NT, int CIN, int LIN, int LOUT, int STRIDE, int ROFF,
         int OUTMODE, int NS, bool ROWBIAS, bool AF32, bool OUTF32>
__global__ void __launch_bounds__(512, 1)
gemm_kernel(const float* __restrict__ Af32,
            const bf16* __restrict__ Ahi, const bf16* __restrict__ Alo,
            const bf16* __restrict__ Whi, const bf16* __restrict__ Wlo,
            const float* __restrict__ bias,
            float* __restrict__ Of32, bf16* __restrict__ Ohi,
            bf16* __restrict__ Olo)
{
    constexpr int BK = 64;
    constexpr int NITER = KTOT / BK;
    constexpr int MT = 256;                   // CTA M tile
    constexpr int ASZ = MT * 128;             // bytes per A plane (32 KB)
    constexpr int BSZ = NT * 128;
    constexpr int BUFB = 2 * ASZ + 2 * BSZ;
    constexpr int NH = NT / 2;                // n per warp
    constexpr int NI = NH / 8;                // n8 tiles per warp
    constexpr int NL = NH / 16;               // ldmatrix.x4 calls per plane
    constexpr int BREP = NT / 64;             // B loader reps (512 thr)

    extern __shared__ __align__(1024) char smem_c[];
    const uint32_t smem0 = cvta_smem(smem_c);

    const int tid = threadIdx.x;
    const int lane = tid & 31;
    const int wid = tid >> 5;
    const int warpM = wid >> 1;               // 0..7
    const int warpN = wid & 1;
    const int n0 = blockIdx.x * NT;
    const int m0 = blockIdx.y * MT;

    float acc[2][NI][4];
    #pragma unroll
    for (int mt = 0; mt < 2; ++mt)
        #pragma unroll
        for (int nt = 0; nt < NI; ++nt)
            #pragma unroll
            for (int e = 0; e < 4; ++e) acc[mt][nt][e] = 0.f;

    // ---- loaders -----------------------------------------------------------
    auto load_tiles = [&](int it, int buf) {
        const int k0 = it * BK;
        const uint32_t sb = smem0 + buf * BUFB;
        #pragma unroll
        for (int rep = 0; rep < 4; ++rep) {           // A: 256 rows x 8 x 16B
            int v = tid + rep * 512;
            int row = v >> 3, q = v & 7;
            int m = m0 + row;
            int b = m / LOUT, p = m - b * LOUT;
            int k = k0 + q * 8;
            int j = k / CIN, i = k - j * CIN;
            int r = STRIDE * p + j + ROFF;
            bool ok = (r >= 0) && (r < LIN);
            size_t off = (size_t)b * ((size_t)LIN * CIN) + (size_t)r * CIN + i;
            uint32_t so = row * 128 + ((q * 16) ^ ((row & 7) << 4));
            int sz = ok ? 16 : 0;
            cpa16(sb + so, Ahi + off, sz);
            cpa16(sb + ASZ + so, Alo + off, sz);
        }
        #pragma unroll
        for (int rep = 0; rep < BREP; ++rep) {        // B: NT rows x 8 x 16B
            int v = tid + rep * 512;
            int n = v >> 3, q = v & 7;
            size_t off = (size_t)(n0 + n) * KTOT + k0 + q * 8;
            uint32_t so = n * 128 + ((q * 16) ^ ((n & 7) << 4));
            cpa16(sb + 2 * ASZ + so, Whi + off, 16);
            cpa16(sb + 2 * ASZ + BSZ + so, Wlo + off, 16);
        }
    };

    if constexpr (AF32) {
        // stage-A: single K-tile, fp32 -> split bf16 in registers, sync stores
        #pragma unroll
        for (int rep = 0; rep < 8; ++rep) {           // 256 rows x 16 x 8B
            int v = tid + rep * 512;
            int row = v >> 4, q = v & 15;
            int m = m0 + row;
            int b = m / LOUT, p = m - b * LOUT;
            int i = q * 4;
            int r = p + ROFF;
            bool ok = (r >= 0) && (r < LIN);
            float4 val = ok ? *reinterpret_cast<const float4*>(
                                  Af32 + (size_t)b * ((size_t)LIN * CIN) +
                                  (size_t)r * CIN + i)
                            : make_float4(0.f, 0.f, 0.f, 0.f);
            bf16 h0, h1, h2, h3, l0, l1, l2, l3;
            split2(val.x, h0, l0); split2(val.y, h1, l1);
            split2(val.z, h2, l2); split2(val.w, h3, l3);
            uint32_t so = row * 128 + ((q * 8) ^ ((row & 7) << 4));
            *reinterpret_cast<uint2*>(smem_c + so) =
                make_uint2(pack2(h0, h1), pack2(h2, h3));
            *reinterpret_cast<uint2*>(smem_c + ASZ + so) =
                make_uint2(pack2(l0, l1), pack2(l2, l3));
        }
        #pragma unroll
        for (int rep = 0; rep < BREP; ++rep) {        // B sync copy
            int v = tid + rep * 512;
            int n = v >> 3, q = v & 7;
            size_t off = (size_t)(n0 + n) * KTOT + q * 8;
            uint32_t so = n * 128 + ((q * 16) ^ ((n & 7) << 4));
            *reinterpret_cast<uint4*>(smem_c + 2 * ASZ + so) =
                *reinterpret_cast<const uint4*>(Whi + off);
            *reinterpret_cast<uint4*>(smem_c + 2 * ASZ + BSZ + so) =
                *reinterpret_cast<const uint4*>(Wlo + off);
        }
        __syncthreads();
    } else {
        load_tiles(0, 0);
        cp_commit();
    }

    // ---- per-lane ldmatrix addressing constants ----------------------------
    const uint32_t aSwz = (uint32_t)(lane & 7) << 4;
    const uint32_t kbBase = (uint32_t)(lane >> 4) << 4;
    uint32_t rowA[2], rowB[NL];
    #pragma unroll
    for (int mt = 0; mt < 2; ++mt)
        rowA[mt] = (uint32_t)(warpM * 32 + mt * 16 + (lane & 15)) * 128;
    #pragma unroll
    for (int c = 0; c < NL; ++c)
        rowB[c] = (uint32_t)(warpN * NH + c * 16 + (lane & 15)) * 128;

    // ---- mainloop: 2-stage pipeline ----------------------------------------
    for (int it = 0; it < NITER; ++it) {
        int buf = it & 1;
        if constexpr (!AF32) {
            if (it + 1 < NITER) {
                load_tiles(it + 1, buf ^ 1);
                cp_commit();
                asm volatile("cp.async.wait_group 1;" ::: "memory");
            } else {
                asm volatile("cp.async.wait_group 0;" ::: "memory");
            }
            __syncthreads();
        } else {
            buf = 0;
        }

        const uint32_t sAh = smem0 + buf * BUFB;
        const uint32_t sAl = sAh + ASZ;
        const uint32_t sBh = sAl + ASZ;
        const uint32_t sBl = sBh + BSZ;

        #pragma unroll
        for (int ks = 0; ks < 4; ++ks) {
            const uint32_t kb = ((uint32_t)(ks * 32) + kbBase) ^ aSwz;
            uint32_t ah[2][4], al[2][4];
            #pragma unroll
            for (int mt = 0; mt < 2; ++mt) {
                LDM4(ah[mt], sAh + rowA[mt] + kb);
                LDM4(al[mt], sAl + rowA[mt] + kb);
            }
            #pragma unroll
            for (int c = 0; c < NL; ++c) {
                uint32_t bh[4], bl[4];
                LDM4(bh, sBh + rowB[c] + kb);
                LDM4(bl, sBl + rowB[c] + kb);
                #pragma unroll
                for (int mt = 0; mt < 2; ++mt) {
                    mma16816(acc[mt][2 * c + 0], ah[mt], bh[0], bh[2]);
                    mma16816(acc[mt][2 * c + 1], ah[mt], bh[1], bh[3]);
                    mma16816(acc[mt][2 * c + 0], ah[mt], bl[0], bl[2]);
                    mma16816(acc[mt][2 * c + 1], ah[mt], bl[1], bl[3]);
                    mma16816(acc[mt][2 * c + 0], al[mt], bh[0], bh[2]);
                    mma16816(acc[mt][2 * c + 1], al[mt], bh[1], bh[3]);
                }
            }
        }
        if constexpr (!AF32) {
            if (it + 1 < NITER) __syncthreads();   // protect buf before reissue
        }
    }

    // ---- epilogue (register accumulators) ----------------------------------
    const int tr = lane >> 2;
    const int tc = (lane & 3) * 2;
    #pragma unroll
    for (int mt = 0; mt < 2; ++mt) {
        #pragma unroll
        for (int half = 0; half < 2; ++half) {     // d0,d1 then d2,d3 (row+8)
            const int m = m0 + warpM * 32 + mt * 16 + tr + half * 8;
            const int bb = m / LOUT;
            const int pp = m - bb * LOUT;
            #pragma unroll
            for (int nt = 0; nt < NI; ++nt) {
                const int n = n0 + warpN * NH + nt * 8 + tc;
                const float d0 = acc[mt][nt][half * 2 + 0];
                const float d1 = acc[mt][nt][half * 2 + 1];
                float b0, b1;
                if constexpr (ROWBIAS) {
                    b0 = bias[(size_t)bb * 64 + n];
                    b1 = bias[(size_t)bb * 64 + n + 1];
                } else {
                    b0 = bias[n];
                    b1 = bias[n + 1];
                }
                const float v0 = fmaxf(d0 + b0, 0.f);
                const float v1 = fmaxf(d1 + b1, 0.f);
                size_t o;
                if constexpr (OUTMODE == 0) {
                    o = (size_t)m * NS + n;
                } else {
                    // z layout: z[b][p*256 + n] (contiguous channels-last)
                    o = (size_t)bb * 16640 + (size_t)pp * 256 + n;
                }
                if constexpr (OUTF32) {
                    *reinterpret_cast<float2*>(Of32 + o) = make_float2(v0, v1);
                } else {
                    bf16 h0, h1, l0, l1;
                    split2(v0, h0, l0);
                    split2(v1, h1, l1);
                    *reinterpret_cast<uint32_t*>(Ohi + o) = pack2(h0, h1);
                    *reinterpret_cast<uint32_t*>(Olo + o) = pack2(l0, l1);
                }
            }
        }
    }
}

// ---------------------------------------------------------------------------
// Weight prep. Small weights in one kernel; fc1 permute in a dedicated
// kernel with a padded SMEM transpose (coalesced reads AND writes).
// ---------------------------------------------------------------------------
#define PREP_SA   4096
#define PREP_C1   (128 * 192)
#define PREP_C2   (256 * 384)
#define PREP_C3   (256 * 768)
#define PREP_SMALL (PREP_SA + PREP_C1 + PREP_C2 + PREP_C3)

__global__ void prep_small_kernel(
    const float* __restrict__ Wp, const float* __restrict__ W1,
    const float* __restrict__ W2, const float* __restrict__ W3,
    bf16* wah, bf16* wal, bf16* w1h, bf16* w1l, bf16* w2h, bf16* w2l,
    bf16* w3h, bf16* w3l)
{
    int idx = blockIdx.x * 256 + threadIdx.x;
    if (idx >= PREP_SMALL) return;
    bf16 h, l;
    if (idx < PREP_SA) {
        int p = idx >> 6, i = idx & 63;
        split2(Wp[p * 128 + i * 2 + 1], h, l);
        wah[idx] = h; wal[idx] = l;
        return;
    }
    idx -= PREP_SA;
    if (idx < PREP_C1) {
        int o = idx / 192, rem = idx - o * 192;
        int i = rem / 3, j = rem - i * 3;
        split2(W1[idx], h, l);
        int out = o * 192 + j * 64 + i;
        w1h[out] = h; w1l[out] = l;
        return;
    }
    idx -= PREP_C1;
    if (idx < PREP_C2) {
        int o = idx / 384, rem = idx - o * 384;
        int i = rem / 3, j = rem - i * 3;
        split2(W2[idx], h, l);
        int out = o * 384 + j * 128 + i;
        w2h[out] = h; w2l[out] = l;
        return;
    }
    idx -= PREP_C2;
    {
        int o = idx / 768, rem = idx - o * 768;
        int i = rem / 3, j = rem - i * 3;
        split2(W3[idx], h, l);
        int out = o * 768 + j * 256 + i;
        w3h[out] = h; w3l[out] = l;
    }
}

// fc1 permute: one block per output row n. Conv part old k = c*64+p is
// transposed to k' = p*256+c via padded smem (stride 65 -> conflict-free).
__global__ void __launch_bounds__(256) prep_fc_kernel(
    const float* __restrict__ Wfc1, bf16* __restrict__ wfh,
    bf16* __restrict__ wfl)
{
    extern __shared__ float s[];               // 256*65 floats
    const int n = blockIdx.x, tid = threadIdx.x;
    const float* src = Wfc1 + (size_t)n * 16640;
    for (int k = tid; k < 16384; k += 256) {   // coalesced read
        int c = k >> 6, p = k & 63;
        s[c * 65 + p] = src[k];
    }
    __syncthreads();
    bf16* dh = wfh + (size_t)n * 16640;
    bf16* dl = wfl + (size_t)n * 16640;
    for (int k2 = tid; k2 < 16384; k2 += 256) { // coalesced write
        int p = k2 >> 8, c = k2 & 255;
        bf16 h, l;
        split2(s[c * 65 + p], h, l);
        dh[k2] = h; dl[k2] = l;
    }
    for (int k2 = 16384 + tid; k2 < 16640; k2 += 256) {
        bf16 h, l;
        split2(src[k2], h, l);
        dh[k2] = h; dl[k2] = l;
    }
}

// s0[b][p] = bp[p] + sum_i Wp[p][i][0] * x[b][0][i]
__global__ void __launch_bounds__(64) s0_kernel(
    const float* __restrict__ x, const float* __restrict__ Wp,
    const float* __restrict__ bp, float* __restrict__ s0)
{
    __shared__ float xs[64];
    int b = blockIdx.x, t = threadIdx.x;
    xs[t] = x[(size_t)b * 16384 + t];
    __syncthreads();
    float acc = bp[t];
    #pragma unroll 16
    for (int i = 0; i < 64; ++i) acc += Wp[t * 128 + i * 2] * xs[i];
    s0[b * 64 + t] = acc;
}

// Branch MLP -> split z[:,16384:]
__global__ void __launch_bounds__(256) branch_kernel(
    const float* __restrict__ x,
    const float* __restrict__ Wb1, const float* __restrict__ bb1,
    const float* __restrict__ Wb2, const float* __restrict__ bb2,
    const float* __restrict__ Wb3, const float* __restrict__ bb3,
    bf16* __restrict__ zh, bf16* __restrict__ zl)
{
    __shared__ float x0s[64], f1s[64], f2s[128];
    const int tid = threadIdx.x, b = blockIdx.x;
    if (tid < 64) x0s[tid] = x[(size_t)b * 16384 + tid];
    __syncthreads();
    if (tid < 64) {
        float acc = bb1[tid];
        #pragma unroll 8
        for (int i = 0; i < 64; i++) acc += Wb1[tid * 64 + i] * x0s[i];
        f1s[tid] = fmaxf(acc, 0.f);
    }
    __syncthreads();
    if (tid < 128) {
        float acc = bb2[tid];
        #pragma unroll 8
        for (int i = 0; i < 64; i++) acc += Wb2[tid * 64 + i] * f1s[i];
        f2s[tid] = fmaxf(acc, 0.f);
    }
    __syncthreads();
    {
        float acc = bb3[tid];
        #pragma unroll 8
        for (int i = 0; i < 128; i++) acc += Wb3[tid * 128 + i] * f2s[i];
        float v = fmaxf(acc, 0.f);
        bf16 h, l;
        split2(v, h, l);
        size_t o = (size_t)b * 16640 + 16384 + tid;
        zh[o] = h; zl[o] = l;
    }
}

// fc2
__global__ void __launch_bounds__(128) fc2_kernel(
    const float* __restrict__ f1, const float* __restrict__ W,
    const float* __restrict__ bias, float* __restrict__ out)
{
    __shared__ float red0[4], red1[4];
    const int b = blockIdx.x, tid = threadIdx.x;
    const float* hb = f1 + (size_t)b * 1024;
    float s0 = 0.f, s1 = 0.f;
    for (int k = tid; k < 1024; k += 128) {
        float v = hb[k];
        s0 += v * W[k];
        s1 += v * W[1024 + k];
    }
    #pragma unroll
    for (int off = 16; off > 0; off >>= 1) {
        s0 += __shfl_down_sync(0xffffffffu, s0, off);
        s1 += __shfl_down_sync(0xffffffffu, s1, off);
    }
    if ((tid & 31) == 0) { red0[tid >> 5] = s0; red1[tid >> 5] = s1; }
    __syncthreads();
    if (tid == 0) {
        out[b * 2 + 0] = red0[0] + red0[1] + red0[2] + red0[3] + bias[0];
        out[b * 2 + 1] = red1[0] + red1[1] + red1[2] + red1[3] + bias[1];
    }
}

// ---------------------------------------------------------------------------
// Launch
// ---------------------------------------------------------------------------
extern "C" void kernel_launch(void* const* d_in, const int* in_sizes, int n_in,
                              void* d_out, int out_size)
{
    const float* x    = (const float*)d_in[0];
    const float* Wp   = (const float*)d_in[1];
    const float* bp   = (const float*)d_in[2];
    const float* W1   = (const float*)d_in[3];
    const float* b1   = (const float*)d_in[4];
    const float* W2   = (const float*)d_in[5];
    const float* b2   = (const float*)d_in[6];
    const float* W3   = (const float*)d_in[7];
    const float* b3   = (const float*)d_in[8];
    const float* Wb1  = (const float*)d_in[9];
    const float* bb1  = (const float*)d_in[10];
    const float* Wb2  = (const float*)d_in[11];
    const float* bb2  = (const float*)d_in[12];
    const float* Wb3  = (const float*)d_in[13];
    const float* bb3  = (const float*)d_in[14];
    const float* Wfc1 = (const float*)d_in[15];
    const float* bfc1 = (const float*)d_in[16];
    const float* Wfc2 = (const float*)d_in[17];
    const float* bfc2 = (const float*)d_in[18];
    float* out = (float*)d_out;

    static void *h0h, *h0l, *h1h, *h1l, *h2h, *h2l, *zh, *zl, *f1, *s0;
    static void *wah, *wal, *w1h, *w1l, *w2h, *w2l, *w3h, *w3l, *wfh, *wfl;
    static bool init = false;
    if (!init) {
        cudaGetSymbolAddress(&h0h, g_h0h); cudaGetSymbolAddress(&h0l, g_h0l);
        cudaGetSymbolAddress(&h1h, g_h1h); cudaGetSymbolAddress(&h1l, g_h1l);
        cudaGetSymbolAddress(&h2h, g_h2h); cudaGetSymbolAddress(&h2l, g_h2l);
        cudaGetSymbolAddress(&zh,  g_zh);  cudaGetSymbolAddress(&zl,  g_zl);
        cudaGetSymbolAddress(&f1,  g_f1);  cudaGetSymbolAddress(&s0,  g_s0);
        cudaGetSymbolAddress(&wah, g_wah); cudaGetSymbolAddress(&wal, g_wal);
        cudaGetSymbolAddress(&w1h, g_w1h); cudaGetSymbolAddress(&w1l, g_w1l);
        cudaGetSymbolAddress(&w2h, g_w2h); cudaGetSymbolAddress(&w2l, g_w2l);
        cudaGetSymbolAddress(&w3h, g_w3h); cudaGetSymbolAddress(&w3l, g_w3l);
        cudaGetSymbolAddress(&wfh, g_wfh); cudaGetSymbolAddress(&wfl, g_wfl);

        auto setsm = [](const void* f, int bytes) {
            cudaFuncSetAttribute(f, cudaFuncAttributeMaxDynamicSharedMemorySize, bytes);
        };
        setsm((const void*)gemm_kernel<64, 64, 64, 256, 255, 1, 1, 0, 64, true, true, false>, 81920);
        setsm((const void*)gemm_kernel<192, 128, 64, 255, 255, 1, -1, 0, 128, false, false, false>, 196608);
        setsm((const void*)gemm_kernel<384, 128, 128, 255, 128, 2, -1, 0, 256, false, false, false>, 196608);
        setsm((const void*)gemm_kernel<768, 128, 256, 128, 64, 2, -1, 2, 0, false, false, false>, 196608);
        setsm((const void*)gemm_kernel<16640, 64, 16640, 1, 1, 1, 0, 0, 1024, false, false, true>, 163840);
        setsm((const void*)prep_fc_kernel, 256 * 65 * 4);
        init = true;
    }

    // weight prep
    prep_small_kernel<<<(PREP_SMALL + 255) / 256, 256>>>(
        Wp, W1, W2, W3,
        (bf16*)wah, (bf16*)wal, (bf16*)w1h, (bf16*)w1l, (bf16*)w2h, (bf16*)w2l,
        (bf16*)w3h, (bf16*)w3l);
    prep_fc_kernel<<<1024, 256, 256 * 65 * 4>>>(Wfc1, (bf16*)wfh, (bf16*)wfl);

    // small fp32 side paths
    s0_kernel<<<2048, 64>>>(x, Wp, bp, (float*)s0);
    branch_kernel<<<2048, 256>>>(x, Wb1, bb1, Wb2, bb2, Wb3, bb3,
                                 (bf16*)zh, (bf16*)zl);

    // stage-A: A = x cols 1..255 (fp32->split in-kernel), rowbias = s0
    gemm_kernel<64, 64, 64, 256, 255, 1, 1, 0, 64, true, true, false>
        <<<dim3(1, 2040), 512, 81920>>>(
            x, nullptr, nullptr, (const bf16*)wah, (const bf16*)wal,
            (const float*)s0, nullptr, (bf16*)h0h, (bf16*)h0l);

    // conv1
    gemm_kernel<192, 128, 64, 255, 255, 1, -1, 0, 128, false, false, false>
        <<<dim3(1, 2040), 512, 196608>>>(
            nullptr, (const bf16*)h0h, (const bf16*)h0l,
            (const bf16*)w1h, (const bf16*)w1l, b1,
            nullptr, (bf16*)h1h, (bf16*)h1l);

    // conv2
    gemm_kernel<384, 128, 128, 255, 128, 2, -1, 0, 256, false, false, false>
        <<<dim3(2, 1024), 512, 196608>>>(
            nullptr, (const bf16*)h1h, (const bf16*)h1l,
            (const bf16*)w2h, (const bf16*)w2l, b2,
            nullptr, (bf16*)h2h, (bf16*)h2l);

    // conv3 -> z (contiguous channels-last layout, permuted fc1 k-order)
    gemm_kernel<768, 128, 256, 128, 64, 2, -1, 2, 0, false, false, false>
        <<<dim3(2, 512), 512, 196608>>>(
            nullptr, (const bf16*)h2h, (const bf16*)h2l,
            (const bf16*)w3h, (const bf16*)w3l, b3,
            nullptr, (bf16*)zh, (bf16*)zl);

    // fc1 -> f1 (fp32): 256x64 tiles, grid (16, 8) = 128 CTAs
    gemm_kernel<16640, 64, 16640, 1, 1, 1, 0, 0, 1024, false, false, true>
        <<<dim3(16, 8), 512, 163840>>>(
            nullptr, (const bf16*)zh, (const bf16*)zl,
            (const bf16*)wfh, (const bf16*)wfl, bfc1,
            (float*)f1, nullptr, nullptr);

    fc2_kernel<<<2048, 128>>>((const float*)f1, Wfc2, bfc2, out);
}

// round 7
// speedup vs baseline: 1.1543x; 1.1320x over previous
#include <cuda_runtime.h>
#include <cuda_bf16.h>
#include <cstdint>

typedef __nv_bfloat16 bf16;

// ---------------------------------------------------------------------------
// Static scratch: split bf16 activation planes (channels-last), fp32 f1/s0,
// pre-split weights in im2col k-order (k = j*CIN + i).
// z / Wfc1 use permuted k-order: k' = pos*256 + chan for the conv part.
// ---------------------------------------------------------------------------
__device__ __align__(1024) bf16 g_h0h[(size_t)2048 * 255 * 64];
__device__ __align__(1024) bf16 g_h0l[(size_t)2048 * 255 * 64];
__device__ __align__(1024) bf16 g_h1h[(size_t)2048 * 255 * 128];
__device__ __align__(1024) bf16 g_h1l[(size_t)2048 * 255 * 128];
__device__ __align__(1024) bf16 g_h2h[(size_t)2048 * 128 * 256];
__device__ __align__(1024) bf16 g_h2l[(size_t)2048 * 128 * 256];
__device__ __align__(1024) bf16 g_zh [(size_t)2048 * 16640];
__device__ __align__(1024) bf16 g_zl [(size_t)2048 * 16640];
__device__ __align__(1024) float g_f1[(size_t)2048 * 1024];
__device__ __align__(1024) float g_s0[2048 * 64];
__device__ __align__(1024) bf16 g_wah[64 * 64],   g_wal[64 * 64];
__device__ __align__(1024) bf16 g_w1h[128 * 192], g_w1l[128 * 192];
__device__ __align__(1024) bf16 g_w2h[256 * 384], g_w2l[256 * 384];
__device__ __align__(1024) bf16 g_w3h[256 * 768], g_w3l[256 * 768];
__device__ __align__(1024) bf16 g_wfh[(size_t)1024 * 16640];
__device__ __align__(1024) bf16 g_wfl[(size_t)1024 * 16640];
// transposed fp32 branch/s0 weights: [i][n] layouts for coalesced reads
__device__ __align__(1024) float g_wpt [64 * 64];
__device__ __align__(1024) float g_wb1t[64 * 64];
__device__ __align__(1024) float g_wb2t[64 * 128];
__device__ __align__(1024) float g_wb3t[128 * 256];

// ---------------------------------------------------------------------------
// Helpers (baseline PTX only: mma.sync / ldmatrix / cp.async — no tcgen05)
// ---------------------------------------------------------------------------
__device__ __forceinline__ uint32_t cvta_smem(const void* p) {
    return (uint32_t)__cvta_generic_to_shared(p);
}
__device__ __forceinline__ void cpa16(uint32_t dst, const void* src, int sz) {
    asm volatile("cp.async.cg.shared.global [%0], [%1], 16, %2;"
                 :: "r"(dst), "l"(src), "r"(sz) : "memory");
}
__device__ __forceinline__ void cp_commit() {
    asm volatile("cp.async.commit_group;" ::: "memory");
}
#define LDM4(r, addr)                                                         \
    asm volatile("ldmatrix.sync.aligned.m8n8.x4.shared.b16 "                  \
                 "{%0,%1,%2,%3}, [%4];"                                       \
                 : "=r"((r)[0]), "=r"((r)[1]), "=r"((r)[2]), "=r"((r)[3])     \
                 : "r"(addr))

__device__ __forceinline__ void mma16816(float* d, const uint32_t* a,
                                         uint32_t b0, uint32_t b1) {
    asm volatile(
        "mma.sync.aligned.m16n8k16.row.col.f32.bf16.bf16.f32 "
        "{%0,%1,%2,%3}, {%4,%5,%6,%7}, {%8,%9}, {%0,%1,%2,%3};"
        : "+f"(d[0]), "+f"(d[1]), "+f"(d[2]), "+f"(d[3])
        : "r"(a[0]), "r"(a[1]), "r"(a[2]), "r"(a[3]), "r"(b0), "r"(b1));
}
__device__ __forceinline__ void split2(float v, bf16& h, bf16& l) {
    h = __float2bfloat16(v);
    l = __float2bfloat16(v - __bfloat162float(h));
}
__device__ __forceinline__ uint32_t pack2(bf16 a, bf16 b) {
    return (uint32_t)__bfloat16_as_ushort(a) |
           ((uint32_t)__bfloat16_as_ushort(b) << 16);
}

// ---------------------------------------------------------------------------
// Unified split-bf16 mma.sync GEMM with fused im2col gather.
// D[m,n] = relu(sum_k A(m,k)*B(n,k) + bias); m=(b,p); k=(j,i); r=STRIDE*p+j+ROFF
// 512 threads, CTA tile 256 x NT, BK=64, 16 warps (8M x 2N), warp 32 x NT/2.
// 2-stage cp.async pipeline. XOR-swizzled SMEM, ldmatrix fragments.
// OUTMODE: 0 = out[m*NS + n]; 2 = z layout out[b*16640 + p*256 + n].
// ---------------------------------------------------------------------------
template<int KTOT, int NT, int CIN, int LIN, int LOUT, int STRIDE, int ROFF,
         int OUTMODE, int NS, bool ROWBIAS, bool AF32, bool OUTF32>
__global__ void __launch_bounds__(512, 1)
gemm_kernel(const float* __restrict__ Af32,
            const bf16* __restrict__ Ahi, const bf16* __restrict__ Alo,
            const bf16* __restrict__ Whi, const bf16* __restrict__ Wlo,
            const float* __restrict__ bias,
            float* __restrict__ Of32, bf16* __restrict__ Ohi,
            bf16* __restrict__ Olo)
{
    constexpr int BK = 64;
    constexpr int NITER = KTOT / BK;
    constexpr int MT = 256;                   // CTA M tile
    constexpr int ASZ = MT * 128;             // bytes per A plane (32 KB)
    constexpr int BSZ = NT * 128;
    constexpr int BUFB = 2 * ASZ + 2 * BSZ;
    constexpr int NH = NT / 2;                // n per warp
    constexpr int NI = NH / 8;                // n8 tiles per warp
    constexpr int NL = NH / 16;               // ldmatrix.x4 calls per plane
    constexpr int BREP = NT / 64;             // B loader reps (512 thr)

    extern __shared__ __align__(1024) char smem_c[];
    const uint32_t smem0 = cvta_smem(smem_c);

    const int tid = threadIdx.x;
    const int lane = tid & 31;
    const int wid = tid >> 5;
    const int warpM = wid >> 1;               // 0..7
    const int warpN = wid & 1;
    const int n0 = blockIdx.x * NT;
    const int m0 = blockIdx.y * MT;

    float acc[2][NI][4];
    #pragma unroll
    for (int mt = 0; mt < 2; ++mt)
        #pragma unroll
        for (int nt = 0; nt < NI; ++nt)
            #pragma unroll
            for (int e = 0; e < 4; ++e) acc[mt][nt][e] = 0.f;

    // ---- loaders -----------------------------------------------------------
    auto load_tiles = [&](int it, int buf) {
        const int k0 = it * BK;
        const uint32_t sb = smem0 + buf * BUFB;
        #pragma unroll
        for (int rep = 0; rep < 4; ++rep) {           // A: 256 rows x 8 x 16B
            int v = tid + rep * 512;
            int row = v >> 3, q = v & 7;
            int m = m0 + row;
            int b = m / LOUT, p = m - b * LOUT;
            int k = k0 + q * 8;
            int j = k / CIN, i = k - j * CIN;
            int r = STRIDE * p + j + ROFF;
            bool ok = (r >= 0) && (r < LIN);
            size_t off = (size_t)b * ((size_t)LIN * CIN) + (size_t)r * CIN + i;
            uint32_t so = row * 128 + ((q * 16) ^ ((row & 7) << 4));
            int sz = ok ? 16 : 0;
            cpa16(sb + so, Ahi + off, sz);
            cpa16(sb + ASZ + so, Alo + off, sz);
        }
        #pragma unroll
        for (int rep = 0; rep < BREP; ++rep) {        // B: NT rows x 8 x 16B
            int v = tid + rep * 512;
            int n = v >> 3, q = v & 7;
            size_t off = (size_t)(n0 + n) * KTOT + k0 + q * 8;
            uint32_t so = n * 128 + ((q * 16) ^ ((n & 7) << 4));
            cpa16(sb + 2 * ASZ + so, Whi + off, 16);
            cpa16(sb + 2 * ASZ + BSZ + so, Wlo + off, 16);
        }
    };

    if constexpr (AF32) {
        // stage-A: single K-tile, fp32 -> split bf16 in registers, sync stores
        #pragma unroll
        for (int rep = 0; rep < 8; ++rep) {           // 256 rows x 16 x 8B
            int v = tid + rep * 512;
            int row = v >> 4, q = v & 15;
            int m = m0 + row;
            int b = m / LOUT, p = m - b * LOUT;
            int i = q * 4;
            int r = p + ROFF;
            bool ok = (r >= 0) && (r < LIN);
            float4 val = ok ? *reinterpret_cast<const float4*>(
                                  Af32 + (size_t)b * ((size_t)LIN * CIN) +
                                  (size_t)r * CIN + i)
                            : make_float4(0.f, 0.f, 0.f, 0.f);
            bf16 h0, h1, h2, h3, l0, l1, l2, l3;
            split2(val.x, h0, l0); split2(val.y, h1, l1);
            split2(val.z, h2, l2); split2(val.w, h3, l3);
            uint32_t so = row * 128 + ((q * 8) ^ ((row & 7) << 4));
            *reinterpret_cast<uint2*>(smem_c + so) =
                make_uint2(pack2(h0, h1), pack2(h2, h3));
            *reinterpret_cast<uint2*>(smem_c + ASZ + so) =
                make_uint2(pack2(l0, l1), pack2(l2, l3));
        }
        #pragma unroll
        for (int rep = 0; rep < BREP; ++rep) {        // B sync copy
            int v = tid + rep * 512;
            int n = v >> 3, q = v & 7;
            size_t off = (size_t)(n0 + n) * KTOT + q * 8;
            uint32_t so = n * 128 + ((q * 16) ^ ((n & 7) << 4));
            *reinterpret_cast<uint4*>(smem_c + 2 * ASZ + so) =
                *reinterpret_cast<const uint4*>(Whi + off);
            *reinterpret_cast<uint4*>(smem_c + 2 * ASZ + BSZ + so) =
                *reinterpret_cast<const uint4*>(Wlo + off);
        }
        __syncthreads();
    } else {
        load_tiles(0, 0);
        cp_commit();
    }

    // ---- per-lane ldmatrix addressing constants ----------------------------
    const uint32_t aSwz = (uint32_t)(lane & 7) << 4;
    const uint32_t kbBase = (uint32_t)(lane >> 4) << 4;
    uint32_t rowA[2], rowB[NL];
    #pragma unroll
    for (int mt = 0; mt < 2; ++mt)
        rowA[mt] = (uint32_t)(warpM * 32 + mt * 16 + (lane & 15)) * 128;
    #pragma unroll
    for (int c = 0; c < NL; ++c)
        rowB[c] = (uint32_t)(warpN * NH + c * 16 + (lane & 15)) * 128;

    // ---- mainloop: 2-stage pipeline ----------------------------------------
    for (int it = 0; it < NITER; ++it) {
        int buf = it & 1;
        if constexpr (!AF32) {
            if (it + 1 < NITER) {
                load_tiles(it + 1, buf ^ 1);
                cp_commit();
                asm volatile("cp.async.wait_group 1;" ::: "memory");
            } else {
                asm volatile("cp.async.wait_group 0;" ::: "memory");
            }
            __syncthreads();
        } else {
            buf = 0;
        }

        const uint32_t sAh = smem0 + buf * BUFB;
        const uint32_t sAl = sAh + ASZ;
        const uint32_t sBh = sAl + ASZ;
        const uint32_t sBl = sBh + BSZ;

        #pragma unroll
        for (int ks = 0; ks < 4; ++ks) {
            const uint32_t kb = ((uint32_t)(ks * 32) + kbBase) ^ aSwz;
            uint32_t ah[2][4], al[2][4];
            #pragma unroll
            for (int mt = 0; mt < 2; ++mt) {
                LDM4(ah[mt], sAh + rowA[mt] + kb);
                LDM4(al[mt], sAl + rowA[mt] + kb);
            }
            #pragma unroll
            for (int c = 0; c < NL; ++c) {
                uint32_t bh[4], bl[4];
                LDM4(bh, sBh + rowB[c] + kb);
                LDM4(bl, sBl + rowB[c] + kb);
                #pragma unroll
                for (int mt = 0; mt < 2; ++mt) {
                    mma16816(acc[mt][2 * c + 0], ah[mt], bh[0], bh[2]);
                    mma16816(acc[mt][2 * c + 1], ah[mt], bh[1], bh[3]);
                    mma16816(acc[mt][2 * c + 0], ah[mt], bl[0], bl[2]);
                    mma16816(acc[mt][2 * c + 1], ah[mt], bl[1], bl[3]);
                    mma16816(acc[mt][2 * c + 0], al[mt], bh[0], bh[2]);
                    mma16816(acc[mt][2 * c + 1], al[mt], bh[1], bh[3]);
                }
            }
        }
        if constexpr (!AF32) {
            if (it + 1 < NITER) __syncthreads();   // protect buf before reissue
        }
    }

    // ---- epilogue (register accumulators) ----------------------------------
    const int tr = lane >> 2;
    const int tc = (lane & 3) * 2;
    #pragma unroll
    for (int mt = 0; mt < 2; ++mt) {
        #pragma unroll
        for (int half = 0; half < 2; ++half) {     // d0,d1 then d2,d3 (row+8)
            const int m = m0 + warpM * 32 + mt * 16 + tr + half * 8;
            const int bb = m / LOUT;
            const int pp = m - bb * LOUT;
            #pragma unroll
            for (int nt = 0; nt < NI; ++nt) {
                const int n = n0 + warpN * NH + nt * 8 + tc;
                const float d0 = acc[mt][nt][half * 2 + 0];
                const float d1 = acc[mt][nt][half * 2 + 1];
                float b0, b1;
                if constexpr (ROWBIAS) {
                    b0 = bias[(size_t)bb * 64 + n];
                    b1 = bias[(size_t)bb * 64 + n + 1];
                } else {
                    b0 = bias[n];
                    b1 = bias[n + 1];
                }
                const float v0 = fmaxf(d0 + b0, 0.f);
                const float v1 = fmaxf(d1 + b1, 0.f);
                size_t o;
                if constexpr (OUTMODE == 0) {
                    o = (size_t)m * NS + n;
                } else {
                    // z layout: z[b][p*256 + n] (contiguous channels-last)
                    o = (size_t)bb * 16640 + (size_t)pp * 256 + n;
                }
                if constexpr (OUTF32) {
                    *reinterpret_cast<float2*>(Of32 + o) = make_float2(v0, v1);
                } else {
                    bf16 h0, h1, l0, l1;
                    split2(v0, h0, l0);
                    split2(v1, h1, l1);
                    *reinterpret_cast<uint32_t*>(Ohi + o) = pack2(h0, h1);
                    *reinterpret_cast<uint32_t*>(Olo + o) = pack2(l0, l1);
                }
            }
        }
    }
}

// ---------------------------------------------------------------------------
// Weight prep. Small weights + transposed branch/s0 tables in one kernel;
// fc1 permute in a dedicated kernel (padded SMEM transpose, coalesced).
// ---------------------------------------------------------------------------
#define PREP_SA   4096
#define PREP_C1   (128 * 192)
#define PREP_C2   (256 * 384)
#define PREP_C3   (256 * 768)
#define PREP_WPT  4096
#define PREP_WB1  4096
#define PREP_WB2  8192
#define PREP_WB3  32768
#define PREP_SMALL (PREP_SA + PREP_C1 + PREP_C2 + PREP_C3 + PREP_WPT + \
                    PREP_WB1 + PREP_WB2 + PREP_WB3)

__global__ void prep_small_kernel(
    const float* __restrict__ Wp, const float* __restrict__ W1,
    const float* __restrict__ W2, const float* __restrict__ W3,
    const float* __restrict__ Wb1, const float* __restrict__ Wb2,
    const float* __restrict__ Wb3,
    bf16* wah, bf16* wal, bf16* w1h, bf16* w1l, bf16* w2h, bf16* w2l,
    bf16* w3h, bf16* w3l,
    float* wpt, float* wb1t, float* wb2t, float* wb3t)
{
    int idx = blockIdx.x * 256 + threadIdx.x;
    if (idx >= PREP_SMALL) return;
    bf16 h, l;
    if (idx < PREP_SA) {
        int p = idx >> 6, i = idx & 63;
        split2(Wp[p * 128 + i * 2 + 1], h, l);
        wah[idx] = h; wal[idx] = l;
        return;
    }
    idx -= PREP_SA;
    if (idx < PREP_C1) {
        int o = idx / 192, rem = idx - o * 192;
        int i = rem / 3, j = rem - i * 3;
        split2(W1[idx], h, l);
        int out = o * 192 + j * 64 + i;
        w1h[out] = h; w1l[out] = l;
        return;
    }
    idx -= PREP_C1;
    if (idx < PREP_C2) {
        int o = idx / 384, rem = idx - o * 384;
        int i = rem / 3, j = rem - i * 3;
        split2(W2[idx], h, l);
        int out = o * 384 + j * 128 + i;
        w2h[out] = h; w2l[out] = l;
        return;
    }
    idx -= PREP_C2;
    if (idx < PREP_C3) {
        int o = idx / 768, rem = idx - o * 768;
        int i = rem / 3, j = rem - i * 3;
        split2(W3[idx], h, l);
        int out = o * 768 + j * 256 + i;
        w3h[out] = h; w3l[out] = l;
        return;
    }
    idx -= PREP_C3;
    if (idx < PREP_WPT) {                      // wpt[i*64+p] = Wp[p][i][0]
        int i = idx >> 6, p = idx & 63;
        wpt[idx] = Wp[p * 128 + i * 2];
        return;
    }
    idx -= PREP_WPT;
    if (idx < PREP_WB1) {                      // wb1t[i*64+n] = Wb1[n][i]
        int i = idx >> 6, n = idx & 63;
        wb1t[idx] = Wb1[n * 64 + i];
        return;
    }
    idx -= PREP_WB1;
    if (idx < PREP_WB2) {                      // wb2t[i*128+n] = Wb2[n][i]
        int i = idx >> 7, n = idx & 127;
        wb2t[idx] = Wb2[n * 64 + i];
        return;
    }
    idx -= PREP_WB2;
    {                                          // wb3t[i*256+n] = Wb3[n][i]
        int i = idx >> 8, n = idx & 255;
        wb3t[idx] = Wb3[n * 128 + i];
    }
}

// fc1 permute: one block per output row n. Conv part old k = c*64+p is
// transposed to k' = p*256+c via padded smem (stride 65 -> conflict-free).
__global__ void __launch_bounds__(256) prep_fc_kernel(
    const float* __restrict__ Wfc1, bf16* __restrict__ wfh,
    bf16* __restrict__ wfl)
{
    extern __shared__ float s[];               // 256*65 floats
    const int n = blockIdx.x, tid = threadIdx.x;
    const float* src = Wfc1 + (size_t)n * 16640;
    for (int k = tid; k < 16384; k += 256) {   // coalesced read
        int c = k >> 6, p = k & 63;
        s[c * 65 + p] = src[k];
    }
    __syncthreads();
    bf16* dh = wfh + (size_t)n * 16640;
    bf16* dl = wfl + (size_t)n * 16640;
    for (int k2 = tid; k2 < 16384; k2 += 256) { // coalesced write
        int p = k2 >> 8, c = k2 & 255;
        bf16 h, l;
        split2(s[c * 65 + p], h, l);
        dh[k2] = h; dl[k2] = l;
    }
    for (int k2 = 16384 + tid; k2 < 16640; k2 += 256) {
        bf16 h, l;
        split2(src[k2], h, l);
        dh[k2] = h; dl[k2] = l;
    }
}

// ---------------------------------------------------------------------------
// Fused branch MLP + s0: 16 batches/block, 256 threads, activations in SMEM,
// transposed weights (coalesced, L1-resident). Writes s0 and z[:,16384:].
// ---------------------------------------------------------------------------
#define BB 16
__global__ void __launch_bounds__(256) branch_s0_kernel(
    const float* __restrict__ x,
    const float* __restrict__ wpt,  const float* __restrict__ bp,
    const float* __restrict__ wb1t, const float* __restrict__ bb1,
    const float* __restrict__ wb2t, const float* __restrict__ bb2,
    const float* __restrict__ wb3t, const float* __restrict__ bb3,
    float* __restrict__ s0, bf16* __restrict__ zh, bf16* __restrict__ zl)
{
    __shared__ float x0s[BB][64];
    __shared__ float f1s[BB][64];
    __shared__ float f2s[BB][128];
    const int tid = threadIdx.x;
    const int b0 = blockIdx.x * BB;

    #pragma unroll
    for (int t = 0; t < BB * 64 / 256; ++t) {
        int idx = tid + t * 256;
        int bs = idx >> 6, i = idx & 63;
        x0s[bs][i] = x[(size_t)(b0 + bs) * 16384 + i];
    }
    __syncthreads();

    // s0 + layer1 (share x0 reads)
    #pragma unroll
    for (int t = 0; t < BB * 64 / 256; ++t) {          // 4 items/thread
        int idx = tid + t * 256;
        int bs = idx >> 6, n = idx & 63;
        float a0 = bp[n], a1 = bb1[n];
        #pragma unroll 8
        for (int i = 0; i < 64; ++i) {
            float xv = x0s[bs][i];
            a0 += wpt[i * 64 + n] * xv;
            a1 += wb1t[i * 64 + n] * xv;
        }
        s0[(size_t)(b0 + bs) * 64 + n] = a0;
        f1s[bs][n] = fmaxf(a1, 0.f);
    }
    __syncthreads();

    #pragma unroll
    for (int t = 0; t < BB * 128 / 256; ++t) {         // 8 items/thread
        int idx = tid + t * 256;
        int bs = idx >> 7, n = idx & 127;
        float a = bb2[n];
        #pragma unroll 8
        for (int i = 0; i < 64; ++i)
            a += wb2t[i * 128 + n] * f1s[bs][i];
        f2s[bs][n] = fmaxf(a, 0.f);
    }
    __syncthreads();

    #pragma unroll
    for (int t = 0; t < BB * 256 / 256; ++t) {         // 16 items/thread
        int idx = tid + t * 256;
        int bs = idx >> 8, n = idx & 255;
        float a = bb3[n];
        #pragma unroll 8
        for (int i = 0; i < 128; ++i)
            a += wb3t[i * 256 + n] * f2s[bs][i];
        float v = fmaxf(a, 0.f);
        bf16 h, l;
        split2(v, h, l);
        size_t o = (size_t)(b0 + bs) * 16640 + 16384 + n;
        zh[o] = h; zl[o] = l;
    }
}

// fc2
__global__ void __launch_bounds__(128) fc2_kernel(
    const float* __restrict__ f1, const float* __restrict__ W,
    const float* __restrict__ bias, float* __restrict__ out)
{
    __shared__ float red0[4], red1[4];
    const int b = blockIdx.x, tid = threadIdx.x;
    const float* hb = f1 + (size_t)b * 1024;
    float s0 = 0.f, s1 = 0.f;
    for (int k = tid; k < 1024; k += 128) {
        float v = hb[k];
        s0 += v * W[k];
        s1 += v * W[1024 + k];
    }
    #pragma unroll
    for (int off = 16; off > 0; off >>= 1) {
        s0 += __shfl_down_sync(0xffffffffu, s0, off);
        s1 += __shfl_down_sync(0xffffffffu, s1, off);
    }
    if ((tid & 31) == 0) { red0[tid >> 5] = s0; red1[tid >> 5] = s1; }
    __syncthreads();
    if (tid == 0) {
        out[b * 2 + 0] = red0[0] + red0[1] + red0[2] + red0[3] + bias[0];
        out[b * 2 + 1] = red1[0] + red1[1] + red1[2] + red1[3] + bias[1];
    }
}

// ---------------------------------------------------------------------------
// Launch
// ---------------------------------------------------------------------------
extern "C" void kernel_launch(void* const* d_in, const int* in_sizes, int n_in,
                              void* d_out, int out_size)
{
    const float* x    = (const float*)d_in[0];
    const float* Wp   = (const float*)d_in[1];
    const float* bp   = (const float*)d_in[2];
    const float* W1   = (const float*)d_in[3];
    const float* b1   = (const float*)d_in[4];
    const float* W2   = (const float*)d_in[5];
    const float* b2   = (const float*)d_in[6];
    const float* W3   = (const float*)d_in[7];
    const float* b3   = (const float*)d_in[8];
    const float* Wb1  = (const float*)d_in[9];
    const float* bb1  = (const float*)d_in[10];
    const float* Wb2  = (const float*)d_in[11];
    const float* bb2  = (const float*)d_in[12];
    const float* Wb3  = (const float*)d_in[13];
    const float* bb3  = (const float*)d_in[14];
    const float* Wfc1 = (const float*)d_in[15];
    const float* bfc1 = (const float*)d_in[16];
    const float* Wfc2 = (const float*)d_in[17];
    const float* bfc2 = (const float*)d_in[18];
    float* out = (float*)d_out;

    static void *h0h, *h0l, *h1h, *h1l, *h2h, *h2l, *zh, *zl, *f1, *s0;
    static void *wah, *wal, *w1h, *w1l, *w2h, *w2l, *w3h, *w3l, *wfh, *wfl;
    static void *wpt, *wb1t, *wb2t, *wb3t;
    static bool init = false;
    if (!init) {
        cudaGetSymbolAddress(&h0h, g_h0h); cudaGetSymbolAddress(&h0l, g_h0l);
        cudaGetSymbolAddress(&h1h, g_h1h); cudaGetSymbolAddress(&h1l, g_h1l);
        cudaGetSymbolAddress(&h2h, g_h2h); cudaGetSymbolAddress(&h2l, g_h2l);
        cudaGetSymbolAddress(&zh,  g_zh);  cudaGetSymbolAddress(&zl,  g_zl);
        cudaGetSymbolAddress(&f1,  g_f1);  cudaGetSymbolAddress(&s0,  g_s0);
        cudaGetSymbolAddress(&wah, g_wah); cudaGetSymbolAddress(&wal, g_wal);
        cudaGetSymbolAddress(&w1h, g_w1h); cudaGetSymbolAddress(&w1l, g_w1l);
        cudaGetSymbolAddress(&w2h, g_w2h); cudaGetSymbolAddress(&w2l, g_w2l);
        cudaGetSymbolAddress(&w3h, g_w3h); cudaGetSymbolAddress(&w3l, g_w3l);
        cudaGetSymbolAddress(&wfh, g_wfh); cudaGetSymbolAddress(&wfl, g_wfl);
        cudaGetSymbolAddress(&wpt, g_wpt); cudaGetSymbolAddress(&wb1t, g_wb1t);
        cudaGetSymbolAddress(&wb2t, g_wb2t); cudaGetSymbolAddress(&wb3t, g_wb3t);

        auto setsm = [](const void* f, int bytes) {
            cudaFuncSetAttribute(f, cudaFuncAttributeMaxDynamicSharedMemorySize, bytes);
        };
        setsm((const void*)gemm_kernel<64, 64, 64, 256, 255, 1, 1, 0, 64, true, true, false>, 81920);
        setsm((const void*)gemm_kernel<192, 128, 64, 255, 255, 1, -1, 0, 128, false, false, false>, 196608);
        setsm((const void*)gemm_kernel<384, 128, 128, 255, 128, 2, -1, 0, 256, false, false, false>, 196608);
        setsm((const void*)gemm_kernel<768, 128, 256, 128, 64, 2, -1, 2, 0, false, false, false>, 196608);
        setsm((const void*)gemm_kernel<16640, 64, 16640, 1, 1, 1, 0, 0, 1024, false, false, true>, 163840);
        setsm((const void*)prep_fc_kernel, 256 * 65 * 4);
        init = true;
    }

    // weight prep
    prep_small_kernel<<<(PREP_SMALL + 255) / 256, 256>>>(
        Wp, W1, W2, W3, Wb1, Wb2, Wb3,
        (bf16*)wah, (bf16*)wal, (bf16*)w1h, (bf16*)w1l, (bf16*)w2h, (bf16*)w2l,
        (bf16*)w3h, (bf16*)w3l,
        (float*)wpt, (float*)wb1t, (float*)wb2t, (float*)wb3t);
    prep_fc_kernel<<<1024, 256, 256 * 65 * 4>>>(Wfc1, (bf16*)wfh, (bf16*)wfl);

    // fused branch MLP + s0
    branch_s0_kernel<<<2048 / BB, 256>>>(
        x, (const float*)wpt, bp, (const float*)wb1t, bb1,
        (const float*)wb2t, bb2, (const float*)wb3t, bb3,
        (float*)s0, (bf16*)zh, (bf16*)zl);

    // stage-A: A = x cols 1..255 (fp32->split in-kernel), rowbias = s0
    gemm_kernel<64, 64, 64, 256, 255, 1, 1, 0, 64, true, true, false>
        <<<dim3(1, 2040), 512, 81920>>>(
            x, nullptr, nullptr, (const bf16*)wah, (const bf16*)wal,
            (const float*)s0, nullptr, (bf16*)h0h, (bf16*)h0l);

    // conv1
    gemm_kernel<192, 128, 64, 255, 255, 1, -1, 0, 128, false, false, false>
        <<<dim3(1, 2040), 512, 196608>>>(
            nullptr, (const bf16*)h0h, (const bf16*)h0l,
            (const bf16*)w1h, (const bf16*)w1l, b1,
            nullptr, (bf16*)h1h, (bf16*)h1l);

    // conv2
    gemm_kernel<384, 128, 128, 255, 128, 2, -1, 0, 256, false, false, false>
        <<<dim3(2, 1024), 512, 196608>>>(
            nullptr, (const bf16*)h1h, (const bf16*)h1l,
            (const bf16*)w2h, (const bf16*)w2l, b2,
            nullptr, (bf16*)h2h, (bf16*)h2l);

    // conv3 -> z (contiguous channels-last layout, permuted fc1 k-order)
    gemm_kernel<768, 128, 256, 128, 64, 2, -1, 2, 0, false, false, false>
        <<<dim3(2, 512), 512, 196608>>>(
            nullptr, (const bf16*)h2h, (const bf16*)h2l,
            (const bf16*)w3h, (const bf16*)w3l, b3,
            nullptr, (bf16*)zh, (bf16*)zl);

    // fc1 -> f1 (fp32): 256x64 tiles, grid (16, 8) = 128 CTAs
    gemm_kernel<16640, 64, 16640, 1, 1, 1, 0, 0, 1024, false, false, true>
        <<<dim3(16, 8), 512, 163840>>>(
            nullptr, (const bf16*)zh, (const bf16*)zl,
            (const bf16*)wfh, (const bf16*)wfl, bfc1,
            (float*)f1, nullptr, nullptr);

    fc2_kernel<<<2048, 128>>>((const float*)f1, Wfc2, bfc2, out);
}

// round 8
// speedup vs baseline: 1.1634x; 1.0079x over previous
#include <cuda_runtime.h>
#include <cuda_bf16.h>
#include <cstdint>

typedef __nv_bfloat16 bf16;

// ---------------------------------------------------------------------------
// Static scratch: split bf16 activation planes (channels-last), fp32 f1/s0,
// pre-split weights in im2col k-order (k = j*CIN + i).
// z / Wfc1 use permuted k-order: k' = pos*256 + chan for the conv part.
// ---------------------------------------------------------------------------
__device__ __align__(1024) bf16 g_h0h[(size_t)2048 * 255 * 64];
__device__ __align__(1024) bf16 g_h0l[(size_t)2048 * 255 * 64];
__device__ __align__(1024) bf16 g_h1h[(size_t)2048 * 255 * 128];
__device__ __align__(1024) bf16 g_h1l[(size_t)2048 * 255 * 128];
__device__ __align__(1024) bf16 g_h2h[(size_t)2048 * 128 * 256];
__device__ __align__(1024) bf16 g_h2l[(size_t)2048 * 128 * 256];
__device__ __align__(1024) bf16 g_zh [(size_t)2048 * 16640];
__device__ __align__(1024) bf16 g_zl [(size_t)2048 * 16640];
__device__ __align__(1024) float g_f1[(size_t)2048 * 1024];
__device__ __align__(1024) float g_s0[2048 * 64];
__device__ __align__(1024) bf16 g_wah[64 * 64],   g_wal[64 * 64];
__device__ __align__(1024) bf16 g_w1h[128 * 192], g_w1l[128 * 192];
__device__ __align__(1024) bf16 g_w2h[256 * 384], g_w2l[256 * 384];
__device__ __align__(1024) bf16 g_w3h[256 * 768], g_w3l[256 * 768];
__device__ __align__(1024) bf16 g_wfh[(size_t)1024 * 16640];
__device__ __align__(1024) bf16 g_wfl[(size_t)1024 * 16640];
// transposed fp32 branch/s0 weights: [i][n] layouts for coalesced reads
__device__ __align__(1024) float g_wpt [64 * 64];
__device__ __align__(1024) float g_wb1t[64 * 64];
__device__ __align__(1024) float g_wb2t[64 * 128];
__device__ __align__(1024) float g_wb3t[128 * 256];

// ---------------------------------------------------------------------------
// Helpers (baseline PTX only: mma.sync / ldmatrix / cp.async — no tcgen05)
// ---------------------------------------------------------------------------
__device__ __forceinline__ uint32_t cvta_smem(const void* p) {
    return (uint32_t)__cvta_generic_to_shared(p);
}
__device__ __forceinline__ void cpa16(uint32_t dst, const void* src, int sz) {
    asm volatile("cp.async.cg.shared.global [%0], [%1], 16, %2;"
                 :: "r"(dst), "l"(src), "r"(sz) : "memory");
}
__device__ __forceinline__ void cp_commit() {
    asm volatile("cp.async.commit_group;" ::: "memory");
}
#define LDM4(r, addr)                                                         \
    asm volatile("ldmatrix.sync.aligned.m8n8.x4.shared.b16 "                  \
                 "{%0,%1,%2,%3}, [%4];"                                       \
                 : "=r"((r)[0]), "=r"((r)[1]), "=r"((r)[2]), "=r"((r)[3])     \
                 : "r"(addr))

__device__ __forceinline__ void mma16816(float* d, const uint32_t* a,
                                         uint32_t b0, uint32_t b1) {
    asm volatile(
        "mma.sync.aligned.m16n8k16.row.col.f32.bf16.bf16.f32 "
        "{%0,%1,%2,%3}, {%4,%5,%6,%7}, {%8,%9}, {%0,%1,%2,%3};"
        : "+f"(d[0]), "+f"(d[1]), "+f"(d[2]), "+f"(d[3])
        : "r"(a[0]), "r"(a[1]), "r"(a[2]), "r"(a[3]), "r"(b0), "r"(b1));
}
__device__ __forceinline__ void split2(float v, bf16& h, bf16& l) {
    h = __float2bfloat16(v);
    l = __float2bfloat16(v - __bfloat162float(h));
}
__device__ __forceinline__ uint32_t pack2(bf16 a, bf16 b) {
    return (uint32_t)__bfloat16_as_ushort(a) |
           ((uint32_t)__bfloat16_as_ushort(b) << 16);
}

// ---------------------------------------------------------------------------
// Unified split-bf16 mma.sync GEMM with fused im2col gather.
// D[m,n] = relu(sum_k A(m,k)*B(n,k) + bias); m=(b,p); k=(j,i); r=STRIDE*p+j+ROFF
// 256 threads, CTA tile 128 x NT, BK=64, 8 warps as 2M x 4N; warp tile
// 64 x NT/4 (mt=4) -> LDSM:HMMA ratio 1:6 at NT=256. 2-stage cp.async pipe.
// OUTMODE: 0 = out[m*NS + n]; 2 = z layout out[b*16640 + p*256 + n].
// ---------------------------------------------------------------------------
template<int KTOT, int NT, int CIN, int LIN, int LOUT, int STRIDE, int ROFF,
         int OUTMODE, int NS, bool ROWBIAS, bool AF32, bool OUTF32>
__global__ void __launch_bounds__(256, 1)
gemm_kernel(const float* __restrict__ Af32,
            const bf16* __restrict__ Ahi, const bf16* __restrict__ Alo,
            const bf16* __restrict__ Whi, const bf16* __restrict__ Wlo,
            const float* __restrict__ bias,
            float* __restrict__ Of32, bf16* __restrict__ Ohi,
            bf16* __restrict__ Olo)
{
    constexpr int BK = 64;
    constexpr int NITER = KTOT / BK;
    constexpr int MT = 128;                   // CTA M tile
    constexpr int ASZ = MT * 128;             // bytes per A plane (16 KB)
    constexpr int BSZ = NT * 128;
    constexpr int BUFB = 2 * ASZ + 2 * BSZ;
    constexpr int NH = NT / 4;                // n per warp
    constexpr int NI = NH / 8;                // n8 tiles per warp
    constexpr int NL = NH / 16;               // ldmatrix.x4 calls per plane
    constexpr int BREP = NT / 32;             // B loader reps (256 thr)

    extern __shared__ __align__(1024) char smem_c[];
    const uint32_t smem0 = cvta_smem(smem_c);

    const int tid = threadIdx.x;
    const int lane = tid & 31;
    const int wid = tid >> 5;
    const int warpM = wid >> 2;               // 0..1 (64 rows each)
    const int warpN = wid & 3;                // 0..3
    const int n0 = blockIdx.x * NT;
    const int m0 = blockIdx.y * MT;

    float acc[4][NI][4];
    #pragma unroll
    for (int mt = 0; mt < 4; ++mt)
        #pragma unroll
        for (int nt = 0; nt < NI; ++nt)
            #pragma unroll
            for (int e = 0; e < 4; ++e) acc[mt][nt][e] = 0.f;

    // ---- loaders -----------------------------------------------------------
    auto load_tiles = [&](int it, int buf) {
        const int k0 = it * BK;
        const uint32_t sb = smem0 + buf * BUFB;
        #pragma unroll
        for (int rep = 0; rep < 4; ++rep) {           // A: 128 rows x 8 x 16B
            int v = tid + rep * 256;
            int row = v >> 3, q = v & 7;
            int m = m0 + row;
            int b = m / LOUT, p = m - b * LOUT;
            int k = k0 + q * 8;
            int j = k / CIN, i = k - j * CIN;
            int r = STRIDE * p + j + ROFF;
            bool ok = (r >= 0) && (r < LIN);
            size_t off = (size_t)b * ((size_t)LIN * CIN) + (size_t)r * CIN + i;
            uint32_t so = row * 128 + ((q * 16) ^ ((row & 7) << 4));
            int sz = ok ? 16 : 0;
            cpa16(sb + so, Ahi + off, sz);
            cpa16(sb + ASZ + so, Alo + off, sz);
        }
        #pragma unroll
        for (int rep = 0; rep < BREP; ++rep) {        // B: NT rows x 8 x 16B
            int v = tid + rep * 256;
            int n = v >> 3, q = v & 7;
            size_t off = (size_t)(n0 + n) * KTOT + k0 + q * 8;
            uint32_t so = n * 128 + ((q * 16) ^ ((n & 7) << 4));
            cpa16(sb + 2 * ASZ + so, Whi + off, 16);
            cpa16(sb + 2 * ASZ + BSZ + so, Wlo + off, 16);
        }
    };

    if constexpr (AF32) {
        // stage-A: single K-tile, fp32 -> split bf16 in registers, sync stores
        #pragma unroll
        for (int rep = 0; rep < 8; ++rep) {           // 128 rows x 16 x 8B
            int v = tid + rep * 256;
            int row = v >> 4, q = v & 15;
            int m = m0 + row;
            int b = m / LOUT, p = m - b * LOUT;
            int i = q * 4;
            int r = p + ROFF;
            bool ok = (r >= 0) && (r < LIN);
            float4 val = ok ? *reinterpret_cast<const float4*>(
                                  Af32 + (size_t)b * ((size_t)LIN * CIN) +
                                  (size_t)r * CIN + i)
                            : make_float4(0.f, 0.f, 0.f, 0.f);
            bf16 h0, h1, h2, h3, l0, l1, l2, l3;
            split2(val.x, h0, l0); split2(val.y, h1, l1);
            split2(val.z, h2, l2); split2(val.w, h3, l3);
            uint32_t so = row * 128 + ((q * 8) ^ ((row & 7) << 4));
            *reinterpret_cast<uint2*>(smem_c + so) =
                make_uint2(pack2(h0, h1), pack2(h2, h3));
            *reinterpret_cast<uint2*>(smem_c + ASZ + so) =
                make_uint2(pack2(l0, l1), pack2(l2, l3));
        }
        #pragma unroll
        for (int rep = 0; rep < BREP; ++rep) {        // B sync copy
            int v = tid + rep * 256;
            int n = v >> 3, q = v & 7;
            size_t off = (size_t)(n0 + n) * KTOT + q * 8;
            uint32_t so = n * 128 + ((q * 16) ^ ((n & 7) << 4));
            *reinterpret_cast<uint4*>(smem_c + 2 * ASZ + so) =
                *reinterpret_cast<const uint4*>(Whi + off);
            *reinterpret_cast<uint4*>(smem_c + 2 * ASZ + BSZ + so) =
                *reinterpret_cast<const uint4*>(Wlo + off);
        }
        __syncthreads();
    } else {
        load_tiles(0, 0);
        cp_commit();
    }

    // ---- per-lane ldmatrix addressing constants ----------------------------
    const uint32_t aSwz = (uint32_t)(lane & 7) << 4;
    const uint32_t kbBase = (uint32_t)(lane >> 4) << 4;
    uint32_t rowA[4], rowB[NL];
    #pragma unroll
    for (int mt = 0; mt < 4; ++mt)
        rowA[mt] = (uint32_t)(warpM * 64 + mt * 16 + (lane & 15)) * 128;
    #pragma unroll
    for (int c = 0; c < NL; ++c)
        rowB[c] = (uint32_t)(warpN * NH + c * 16 + (lane & 15)) * 128;

    // ---- mainloop: 2-stage pipeline ----------------------------------------
    for (int it = 0; it < NITER; ++it) {
        int buf = it & 1;
        if constexpr (!AF32) {
            if (it + 1 < NITER) {
                load_tiles(it + 1, buf ^ 1);
                cp_commit();
                asm volatile("cp.async.wait_group 1;" ::: "memory");
            } else {
                asm volatile("cp.async.wait_group 0;" ::: "memory");
            }
            __syncthreads();
        } else {
            buf = 0;
        }

        const uint32_t sAh = smem0 + buf * BUFB;
        const uint32_t sAl = sAh + ASZ;
        const uint32_t sBh = sAl + ASZ;
        const uint32_t sBl = sBh + BSZ;

        #pragma unroll
        for (int ks = 0; ks < 4; ++ks) {
            const uint32_t kb = ((uint32_t)(ks * 32) + kbBase) ^ aSwz;
            uint32_t ah[4][4], al[4][4];
            #pragma unroll
            for (int mt = 0; mt < 4; ++mt) {
                LDM4(ah[mt], sAh + rowA[mt] + kb);
                LDM4(al[mt], sAl + rowA[mt] + kb);
            }
            #pragma unroll
            for (int c = 0; c < NL; ++c) {
                uint32_t bh[4], bl[4];
                LDM4(bh, sBh + rowB[c] + kb);
                LDM4(bl, sBl + rowB[c] + kb);
                #pragma unroll
                for (int mt = 0; mt < 4; ++mt) {
                    mma16816(acc[mt][2 * c + 0], ah[mt], bh[0], bh[2]);
                    mma16816(acc[mt][2 * c + 1], ah[mt], bh[1], bh[3]);
                    mma16816(acc[mt][2 * c + 0], ah[mt], bl[0], bl[2]);
                    mma16816(acc[mt][2 * c + 1], ah[mt], bl[1], bl[3]);
                    mma16816(acc[mt][2 * c + 0], al[mt], bh[0], bh[2]);
                    mma16816(acc[mt][2 * c + 1], al[mt], bh[1], bh[3]);
                }
            }
        }
        if constexpr (!AF32) {
            if (it + 1 < NITER) __syncthreads();   // protect buf before reissue
        }
    }

    // ---- epilogue (register accumulators) ----------------------------------
    const int tr = lane >> 2;
    const int tc = (lane & 3) * 2;
    #pragma unroll
    for (int mt = 0; mt < 4; ++mt) {
        #pragma unroll
        for (int half = 0; half < 2; ++half) {     // d0,d1 then d2,d3 (row+8)
            const int m = m0 + warpM * 64 + mt * 16 + tr + half * 8;
            const int bb = m / LOUT;
            const int pp = m - bb * LOUT;
            #pragma unroll
            for (int nt = 0; nt < NI; ++nt) {
                const int n = n0 + warpN * NH + nt * 8 + tc;
                const float d0 = acc[mt][nt][half * 2 + 0];
                const float d1 = acc[mt][nt][half * 2 + 1];
                float b0, b1;
                if constexpr (ROWBIAS) {
                    b0 = bias[(size_t)bb * 64 + n];
                    b1 = bias[(size_t)bb * 64 + n + 1];
                } else {
                    b0 = bias[n];
                    b1 = bias[n + 1];
                }
                const float v0 = fmaxf(d0 + b0, 0.f);
                const float v1 = fmaxf(d1 + b1, 0.f);
                size_t o;
                if constexpr (OUTMODE == 0) {
                    o = (size_t)m * NS + n;
                } else {
                    // z layout: z[b][p*256 + n] (contiguous channels-last)
                    o = (size_t)bb * 16640 + (size_t)pp * 256 + n;
                }
                if constexpr (OUTF32) {
                    *reinterpret_cast<float2*>(Of32 + o) = make_float2(v0, v1);
                } else {
                    bf16 h0, h1, l0, l1;
                    split2(v0, h0, l0);
                    split2(v1, h1, l1);
                    *reinterpret_cast<uint32_t*>(Ohi + o) = pack2(h0, h1);
                    *reinterpret_cast<uint32_t*>(Olo + o) = pack2(l0, l1);
                }
            }
        }
    }
}

// ---------------------------------------------------------------------------
// Weight prep. Small weights + transposed branch/s0 tables in one kernel;
// fc1 permute in a dedicated kernel (padded SMEM transpose, coalesced).
// ---------------------------------------------------------------------------
#define PREP_SA   4096
#define PREP_C1   (128 * 192)
#define PREP_C2   (256 * 384)
#define PREP_C3   (256 * 768)
#define PREP_WPT  4096
#define PREP_WB1  4096
#define PREP_WB2  8192
#define PREP_WB3  32768
#define PREP_SMALL (PREP_SA + PREP_C1 + PREP_C2 + PREP_C3 + PREP_WPT + \
                    PREP_WB1 + PREP_WB2 + PREP_WB3)

__global__ void prep_small_kernel(
    const float* __restrict__ Wp, const float* __restrict__ W1,
    const float* __restrict__ W2, const float* __restrict__ W3,
    const float* __restrict__ Wb1, const float* __restrict__ Wb2,
    const float* __restrict__ Wb3,
    bf16* wah, bf16* wal, bf16* w1h, bf16* w1l, bf16* w2h, bf16* w2l,
    bf16* w3h, bf16* w3l,
    float* wpt, float* wb1t, float* wb2t, float* wb3t)
{
    int idx = blockIdx.x * 256 + threadIdx.x;
    if (idx >= PREP_SMALL) return;
    bf16 h, l;
    if (idx < PREP_SA) {
        int p = idx >> 6, i = idx & 63;
        split2(Wp[p * 128 + i * 2 + 1], h, l);
        wah[idx] = h; wal[idx] = l;
        return;
    }
    idx -= PREP_SA;
    if (idx < PREP_C1) {
        int o = idx / 192, rem = idx - o * 192;
        int i = rem / 3, j = rem - i * 3;
        split2(W1[idx], h, l);
        int out = o * 192 + j * 64 + i;
        w1h[out] = h; w1l[out] = l;
        return;
    }
    idx -= PREP_C1;
    if (idx < PREP_C2) {
        int o = idx / 384, rem = idx - o * 384;
        int i = rem / 3, j = rem - i * 3;
        split2(W2[idx], h, l);
        int out = o * 384 + j * 128 + i;
        w2h[out] = h; w2l[out] = l;
        return;
    }
    idx -= PREP_C2;
    if (idx < PREP_C3) {
        int o = idx / 768, rem = idx - o * 768;
        int i = rem / 3, j = rem - i * 3;
        split2(W3[idx], h, l);
        int out = o * 768 + j * 256 + i;
        w3h[out] = h; w3l[out] = l;
        return;
    }
    idx -= PREP_C3;
    if (idx < PREP_WPT) {                      // wpt[i*64+p] = Wp[p][i][0]
        int i = idx >> 6, p = idx & 63;
        wpt[idx] = Wp[p * 128 + i * 2];
        return;
    }
    idx -= PREP_WPT;
    if (idx < PREP_WB1) {                      // wb1t[i*64+n] = Wb1[n][i]
        int i = idx >> 6, n = idx & 63;
        wb1t[idx] = Wb1[n * 64 + i];
        return;
    }
    idx -= PREP_WB1;
    if (idx < PREP_WB2) {                      // wb2t[i*128+n] = Wb2[n][i]
        int i = idx >> 7, n = idx & 127;
        wb2t[idx] = Wb2[n * 64 + i];
        return;
    }
    idx -= PREP_WB2;
    {                                          // wb3t[i*256+n] = Wb3[n][i]
        int i = idx >> 8, n = idx & 255;
        wb3t[idx] = Wb3[n * 128 + i];
    }
}

// fc1 permute: one block per output row n. Conv part old k = c*64+p is
// transposed to k' = p*256+c via padded smem (stride 65 -> conflict-free).
__global__ void __launch_bounds__(256) prep_fc_kernel(
    const float* __restrict__ Wfc1, bf16* __restrict__ wfh,
    bf16* __restrict__ wfl)
{
    extern __shared__ float s[];               // 256*65 floats
    const int n = blockIdx.x, tid = threadIdx.x;
    const float* src = Wfc1 + (size_t)n * 16640;
    for (int k = tid; k < 16384; k += 256) {   // coalesced read
        int c = k >> 6, p = k & 63;
        s[c * 65 + p] = src[k];
    }
    __syncthreads();
    bf16* dh = wfh + (size_t)n * 16640;
    bf16* dl = wfl + (size_t)n * 16640;
    for (int k2 = tid; k2 < 16384; k2 += 256) { // coalesced write
        int p = k2 >> 8, c = k2 & 255;
        bf16 h, l;
        split2(s[c * 65 + p], h, l);
        dh[k2] = h; dl[k2] = l;
    }
    for (int k2 = 16384 + tid; k2 < 16640; k2 += 256) {
        bf16 h, l;
        split2(src[k2], h, l);
        dh[k2] = h; dl[k2] = l;
    }
}

// ---------------------------------------------------------------------------
// Fused branch MLP + s0: 16 batches/block, 256 threads, activations in SMEM,
// transposed weights (coalesced, L1-resident). Writes s0 and z[:,16384:].
// ---------------------------------------------------------------------------
#define BB 16
__global__ void __launch_bounds__(256) branch_s0_kernel(
    const float* __restrict__ x,
    const float* __restrict__ wpt,  const float* __restrict__ bp,
    const float* __restrict__ wb1t, const float* __restrict__ bb1,
    const float* __restrict__ wb2t, const float* __restrict__ bb2,
    const float* __restrict__ wb3t, const float* __restrict__ bb3,
    float* __restrict__ s0, bf16* __restrict__ zh, bf16* __restrict__ zl)
{
    __shared__ float x0s[BB][64];
    __shared__ float f1s[BB][64];
    __shared__ float f2s[BB][128];
    const int tid = threadIdx.x;
    const int b0 = blockIdx.x * BB;

    #pragma unroll
    for (int t = 0; t < BB * 64 / 256; ++t) {
        int idx = tid + t * 256;
        int bs = idx >> 6, i = idx & 63;
        x0s[bs][i] = x[(size_t)(b0 + bs) * 16384 + i];
    }
    __syncthreads();

    // s0 + layer1 (share x0 reads)
    #pragma unroll
    for (int t = 0; t < BB * 64 / 256; ++t) {          // 4 items/thread
        int idx = tid + t * 256;
        int bs = idx >> 6, n = idx & 63;
        float a0 = bp[n], a1 = bb1[n];
        #pragma unroll 8
        for (int i = 0; i < 64; ++i) {
            float xv = x0s[bs][i];
            a0 += wpt[i * 64 + n] * xv;
            a1 += wb1t[i * 64 + n] * xv;
        }
        s0[(size_t)(b0 + bs) * 64 + n] = a0;
        f1s[bs][n] = fmaxf(a1, 0.f);
    }
    __syncthreads();

    #pragma unroll
    for (int t = 0; t < BB * 128 / 256; ++t) {         // 8 items/thread
        int idx = tid + t * 256;
        int bs = idx >> 7, n = idx & 127;
        float a = bb2[n];
        #pragma unroll 8
        for (int i = 0; i < 64; ++i)
            a += wb2t[i * 128 + n] * f1s[bs][i];
        f2s[bs][n] = fmaxf(a, 0.f);
    }
    __syncthreads();

    #pragma unroll
    for (int t = 0; t < BB * 256 / 256; ++t) {         // 16 items/thread
        int idx = tid + t * 256;
        int bs = idx >> 8, n = idx & 255;
        float a = bb3[n];
        #pragma unroll 8
        for (int i = 0; i < 128; ++i)
            a += wb3t[i * 256 + n] * f2s[bs][i];
        float v = fmaxf(a, 0.f);
        bf16 h, l;
        split2(v, h, l);
        size_t o = (size_t)(b0 + bs) * 16640 + 16384 + n;
        zh[o] = h; zl[o] = l;
    }
}

// fc2
__global__ void __launch_bounds__(128) fc2_kernel(
    const float* __restrict__ f1, const float* __restrict__ W,
    const float* __restrict__ bias, float* __restrict__ out)
{
    __shared__ float red0[4], red1[4];
    const int b = blockIdx.x, tid = threadIdx.x;
    const float* hb = f1 + (size_t)b * 1024;
    float s0 = 0.f, s1 = 0.f;
    for (int k = tid; k < 1024; k += 128) {
        float v = hb[k];
        s0 += v * W[k];
        s1 += v * W[1024 + k];
    }
    #pragma unroll
    for (int off = 16; off > 0; off >>= 1) {
        s0 += __shfl_down_sync(0xffffffffu, s0, off);
        s1 += __shfl_down_sync(0xffffffffu, s1, off);
    }
    if ((tid & 31) == 0) { red0[tid >> 5] = s0; red1[tid >> 5] = s1; }
    __syncthreads();
    if (tid == 0) {
        out[b * 2 + 0] = red0[0] + red0[1] + red0[2] + red0[3] + bias[0];
        out[b * 2 + 1] = red1[0] + red1[1] + red1[2] + red1[3] + bias[1];
    }
}

// ---------------------------------------------------------------------------
// Launch
// ---------------------------------------------------------------------------
extern "C" void kernel_launch(void* const* d_in, const int* in_sizes, int n_in,
                              void* d_out, int out_size)
{
    const float* x    = (const float*)d_in[0];
    const float* Wp   = (const float*)d_in[1];
    const float* bp   = (const float*)d_in[2];
    const float* W1   = (const float*)d_in[3];
    const float* b1   = (const float*)d_in[4];
    const float* W2   = (const float*)d_in[5];
    const float* b2   = (const float*)d_in[6];
    const float* W3   = (const float*)d_in[7];
    const float* b3   = (const float*)d_in[8];
    const float* Wb1  = (const float*)d_in[9];
    const float* bb1  = (const float*)d_in[10];
    const float* Wb2  = (const float*)d_in[11];
    const float* bb2  = (const float*)d_in[12];
    const float* Wb3  = (const float*)d_in[13];
    const float* bb3  = (const float*)d_in[14];
    const float* Wfc1 = (const float*)d_in[15];
    const float* bfc1 = (const float*)d_in[16];
    const float* Wfc2 = (const float*)d_in[17];
    const float* bfc2 = (const float*)d_in[18];
    float* out = (float*)d_out;

    static void *h0h, *h0l, *h1h, *h1l, *h2h, *h2l, *zh, *zl, *f1, *s0;
    static void *wah, *wal, *w1h, *w1l, *w2h, *w2l, *w3h, *w3l, *wfh, *wfl;
    static void *wpt, *wb1t, *wb2t, *wb3t;
    static bool init = false;
    if (!init) {
        cudaGetSymbolAddress(&h0h, g_h0h); cudaGetSymbolAddress(&h0l, g_h0l);
        cudaGetSymbolAddress(&h1h, g_h1h); cudaGetSymbolAddress(&h1l, g_h1l);
        cudaGetSymbolAddress(&h2h, g_h2h); cudaGetSymbolAddress(&h2l, g_h2l);
        cudaGetSymbolAddress(&zh,  g_zh);  cudaGetSymbolAddress(&zl,  g_zl);
        cudaGetSymbolAddress(&f1,  g_f1);  cudaGetSymbolAddress(&s0,  g_s0);
        cudaGetSymbolAddress(&wah, g_wah); cudaGetSymbolAddress(&wal, g_wal);
        cudaGetSymbolAddress(&w1h, g_w1h); cudaGetSymbolAddress(&w1l, g_w1l);
        cudaGetSymbolAddress(&w2h, g_w2h); cudaGetSymbolAddress(&w2l, g_w2l);
        cudaGetSymbolAddress(&w3h, g_w3h); cudaGetSymbolAddress(&w3l, g_w3l);
        cudaGetSymbolAddress(&wfh, g_wfh); cudaGetSymbolAddress(&wfl, g_wfl);
        cudaGetSymbolAddress(&wpt, g_wpt); cudaGetSymbolAddress(&wb1t, g_wb1t);
        cudaGetSymbolAddress(&wb2t, g_wb2t); cudaGetSymbolAddress(&wb3t, g_wb3t);

        auto setsm = [](const void* f, int bytes) {
            cudaFuncSetAttribute(f, cudaFuncAttributeMaxDynamicSharedMemorySize, bytes);
        };
        setsm((const void*)gemm_kernel<64, 64, 64, 256, 255, 1, 1, 0, 64, true, true, false>, 49152);
        setsm((const void*)gemm_kernel<192, 128, 64, 255, 255, 1, -1, 0, 128, false, false, false>, 131072);
        setsm((const void*)gemm_kernel<384, 256, 128, 255, 128, 2, -1, 0, 256, false, false, false>, 196608);
        setsm((const void*)gemm_kernel<768, 256, 256, 128, 64, 2, -1, 2, 0, false, false, false>, 196608);
        setsm((const void*)gemm_kernel<16640, 128, 16640, 1, 1, 1, 0, 0, 1024, false, false, true>, 131072);
        setsm((const void*)prep_fc_kernel, 256 * 65 * 4);
        init = true;
    }

    // weight prep
    prep_small_kernel<<<(PREP_SMALL + 255) / 256, 256>>>(
        Wp, W1, W2, W3, Wb1, Wb2, Wb3,
        (bf16*)wah, (bf16*)wal, (bf16*)w1h, (bf16*)w1l, (bf16*)w2h, (bf16*)w2l,
        (bf16*)w3h, (bf16*)w3l,
        (float*)wpt, (float*)wb1t, (float*)wb2t, (float*)wb3t);
    prep_fc_kernel<<<1024, 256, 256 * 65 * 4>>>(Wfc1, (bf16*)wfh, (bf16*)wfl);

    // fused branch MLP + s0
    branch_s0_kernel<<<2048 / BB, 256>>>(
        x, (const float*)wpt, bp, (const float*)wb1t, bb1,
        (const float*)wb2t, bb2, (const float*)wb3t, bb3,
        (float*)s0, (bf16*)zh, (bf16*)zl);

    // stage-A: A = x cols 1..255 (fp32->split in-kernel), rowbias = s0
    gemm_kernel<64, 64, 64, 256, 255, 1, 1, 0, 64, true, true, false>
        <<<dim3(1, 4080), 256, 49152>>>(
            x, nullptr, nullptr, (const bf16*)wah, (const bf16*)wal,
            (const float*)s0, nullptr, (bf16*)h0h, (bf16*)h0l);

    // conv1
    gemm_kernel<192, 128, 64, 255, 255, 1, -1, 0, 128, false, false, false>
        <<<dim3(1, 4080), 256, 131072>>>(
            nullptr, (const bf16*)h0h, (const bf16*)h0l,
            (const bf16*)w1h, (const bf16*)w1l, b1,
            nullptr, (bf16*)h1h, (bf16*)h1l);

    // conv2
    gemm_kernel<384, 256, 128, 255, 128, 2, -1, 0, 256, false, false, false>
        <<<dim3(1, 2048), 256, 196608>>>(
            nullptr, (const bf16*)h1h, (const bf16*)h1l,
            (const bf16*)w2h, (const bf16*)w2l, b2,
            nullptr, (bf16*)h2h, (bf16*)h2l);

    // conv3 -> z (contiguous channels-last layout, permuted fc1 k-order)
    gemm_kernel<768, 256, 256, 128, 64, 2, -1, 2, 0, false, false, false>
        <<<dim3(1, 1024), 256, 196608>>>(
            nullptr, (const bf16*)h2h, (const bf16*)h2l,
            (const bf16*)w3h, (const bf16*)w3l, b3,
            nullptr, (bf16*)zh, (bf16*)zl);

    // fc1 -> f1 (fp32): 128x128 tiles, grid (8, 16) = 128 CTAs
    gemm_kernel<16640, 128, 16640, 1, 1, 1, 0, 0, 1024, false, false, true>
        <<<dim3(8, 16), 256, 131072>>>(
            nullptr, (const bf16*)zh, (const bf16*)zl,
            (const bf16*)wfh, (const bf16*)wfl, bfc1,
            (float*)f1, nullptr, nullptr);

    fc2_kernel<<<2048, 128>>>((const float*)f1, Wfc2, bfc2, out);
}